// round 3
// baseline (speedup 1.0000x reference)
#include <cuda_runtime.h>
#include <cuda_bf16.h>

// ----------------------------------------------------------------------------
// MPN (chemprop D-MPNN):
//   binput = fbonds @ W_i ; msg = relu(binput)
//   4x: nei = gather-sum(msg, bgraph) ; msg = relu(binput + nei @ W_h)
//   nei_a = gather-sum(msg, agraph) ; ainput=[fatoms|nei_a]
//   ah = relu(ainput @ W_o + b_o) ; out[m] = mean over atoms of molecule m
//
// NOTE: index arrays (agraph/bgraph/mol_idx) are int32 on device — JAX
// downgrades jnp.int64 to int32 without x64 mode.
// Scratch in __device__ globals. kernel_launch performs ONLY kernel launches.
// ----------------------------------------------------------------------------

#define DEPTH 5

// Capacities (problem: n_bonds=160001, H=448, n_atoms=80000, AIN=486)
#define CAP_BONDxH 72000000ll   // >= 160001*448 = 71,680,448
#define CAP_ATOMxAIN 40000000ll // >= 80000*486  = 38,880,000
#define CAP_ATOMxH 36000000ll   // >= 80000*448  = 35,840,000

__device__ float g_binput[CAP_BONDxH];
__device__ float g_msg[CAP_BONDxH];
__device__ float g_nei[CAP_BONDxH];
__device__ float g_ainput[CAP_ATOMxAIN];
__device__ float g_ah[CAP_ATOMxH];

// Device-side scratch pointer table: 0=binput 1=msg 2=nei 3=ainput 4=ah
__device__ float* g_ptrs[5];

__global__ void init_ptrs()
{
    if (threadIdx.x == 0) {
        g_ptrs[0] = g_binput;
        g_ptrs[1] = g_msg;
        g_ptrs[2] = g_nei;
        g_ptrs[3] = g_ainput;
        g_ptrs[4] = g_ah;
    }
}

// ----------------------------------------------------------------------------
// Generic fp32 GEMM: C[M,N] = epilogue(A[M,K](lda) @ B[K,N] + C0 + bias)
// 128x128 tile, BK=8, 256 threads, 8x8 per-thread microtile.
// A/C0/Craw/Crelu may be scratch-table slots (idx >= 0) or external (-1 + ptr).
// ----------------------------------------------------------------------------
#define BM 128
#define BN 128
#define BKK 8
#define TM 8
#define TN 8

__device__ __forceinline__ const float* resolve_c(const float* p, int slot) {
    return (slot >= 0) ? g_ptrs[slot] : p;
}
__device__ __forceinline__ float* resolve_m(float* p, int slot) {
    return (slot >= 0) ? g_ptrs[slot] : p;
}

__global__ __launch_bounds__(256)
void gemm_f32(const float* Ax, int Aslot, int lda,
              const float* __restrict__ B,          // [K,N] row-major (external)
              const float* C0x, int C0slot,         // [M,N] or null
              const float* __restrict__ bias,       // [N] or null
              float* Crawx, int Crawslot,           // [M,N] or null
              float* Crelux, int Creluslot,         // [M,N] or null
              int M, int N, int K)
{
    const float* __restrict__ A    = resolve_c(Ax, Aslot);
    const float* __restrict__ C0   = resolve_c(C0x, C0slot);
    float* __restrict__ Craw  = resolve_m(Crawx, Crawslot);
    float* __restrict__ Crelu = resolve_m(Crelux, Creluslot);

    __shared__ float As[BKK][BM];
    __shared__ float Bs[BKK][BN];

    const int tid = threadIdx.x;
    const int bm = blockIdx.y * BM;
    const int bn = blockIdx.x * BN;
    const int tx = tid & 15;       // 0..15  -> N
    const int ty = tid >> 4;       // 0..15  -> M

    // A-load map: each thread loads 4 scalars: row ar, cols ac..ac+3
    const int ar = tid >> 1;             // 0..127
    const int ac = (tid & 1) * 4;        // 0 or 4
    // B-load map: each thread loads float4: row br, cols bc..bc+3
    const int br = tid >> 5;             // 0..7
    const int bc = (tid & 31) * 4;       // 0..124

    float acc[TM][TN];
    #pragma unroll
    for (int i = 0; i < TM; i++)
        #pragma unroll
        for (int j = 0; j < TN; j++) acc[i][j] = 0.f;

    for (int k0 = 0; k0 < K; k0 += BKK) {
        // load A tile (transposed into As[k][m]) with guards
        {
            long long row = (long long)(bm + ar);
            const bool rok = (bm + ar) < M;
            #pragma unroll
            for (int j = 0; j < 4; j++) {
                int k = k0 + ac + j;
                float v = 0.f;
                if (rok && k < K) v = A[row * lda + k];
                As[ac + j][ar] = v;
            }
        }
        // load B tile
        {
            int k = k0 + br;
            float4 v = make_float4(0.f, 0.f, 0.f, 0.f);
            if (k < K) {
                if (bn + bc + 3 < N) {
                    v = *(const float4*)&B[(long long)k * N + bn + bc];
                } else {
                    float* pv = (float*)&v;
                    #pragma unroll
                    for (int j = 0; j < 4; j++) {
                        int n = bn + bc + j;
                        pv[j] = (n < N) ? B[(long long)k * N + n] : 0.f;
                    }
                }
            }
            *(float4*)&Bs[br][bc] = v;
        }
        __syncthreads();

        #pragma unroll
        for (int kk = 0; kk < BKK; kk++) {
            float a[TM], b[TN];
            #pragma unroll
            for (int i = 0; i < TM; i++) a[i] = As[kk][ty * TM + i];
            #pragma unroll
            for (int j = 0; j < TN; j++) b[j] = Bs[kk][tx * TN + j];
            #pragma unroll
            for (int i = 0; i < TM; i++)
                #pragma unroll
                for (int j = 0; j < TN; j++)
                    acc[i][j] += a[i] * b[j];
        }
        __syncthreads();
    }

    // epilogue
    #pragma unroll
    for (int i = 0; i < TM; i++) {
        int mi = bm + ty * TM + i;
        if (mi >= M) continue;
        long long mrow = (long long)mi * N;
        #pragma unroll
        for (int j = 0; j < TN; j++) {
            int n = bn + tx * TN + j;
            if (n >= N) continue;
            float v = acc[i][j];
            if (C0)   v += C0[mrow + n];
            if (bias) v += bias[n];
            if (Craw)  Craw[mrow + n] = v;
            if (Crelu) Crelu[mrow + n] = fmaxf(v, 0.f);
        }
    }
}

// ----------------------------------------------------------------------------
// Bond neighbor gather-sum: nei[b] = sum_j msg[bgraph[b][j]] (rows of H floats)
// 2 bonds per 128-thread block (64 threads each), float4 vectorized columns.
// ----------------------------------------------------------------------------
__global__ __launch_bounds__(128)
void gather_bonds(const int* __restrict__ bgraph,
                  int n_bonds, int H, int max_nb)
{
    const float* __restrict__ msg = g_ptrs[1];
    float* __restrict__ nei       = g_ptrs[2];

    const int half = threadIdx.x >> 6;                 // 0 or 1
    const int lane = threadIdx.x & 63;                 // 0..63
    const long long b = (long long)blockIdx.x * 2 + half;
    const bool valid = (b < n_bonds);

    __shared__ int idx[2][8];
    if (valid && lane < max_nb)
        idx[half][lane] = bgraph[b * max_nb + lane];
    __syncthreads();
    if (!valid) return;

    const int H4 = H >> 2;
    for (int c = lane; c < H4; c += 64) {
        float4 s = make_float4(0.f, 0.f, 0.f, 0.f);
        #pragma unroll 6
        for (int j = 0; j < max_nb; j++) {
            const float4 v = __ldg((const float4*)&msg[(long long)idx[half][j] * H + c * 4]);
            s.x += v.x; s.y += v.y; s.z += v.z; s.w += v.w;
        }
        *(float4*)&nei[b * H + c * 4] = s;
    }
    for (int c = H4 * 4 + lane; c < H; c += 64) {
        float s = 0.f;
        for (int j = 0; j < max_nb; j++) s += msg[(long long)idx[half][j] * H + c];
        nei[b * H + c] = s;
    }
}

// ----------------------------------------------------------------------------
// Build ainput[a] = [ fatoms[a] (ATOM_DIM) | sum_j msg[agraph[a][j]] (H) ]
// ----------------------------------------------------------------------------
__global__ __launch_bounds__(128)
void build_ainput(const float* __restrict__ fatoms,
                  const int* __restrict__ agraph,
                  int n_atoms, int H, int atom_dim, int max_nb)
{
    const float* __restrict__ msg = g_ptrs[1];
    float* __restrict__ ainput    = g_ptrs[3];

    const long long a = blockIdx.x;
    __shared__ int idx[8];
    if (threadIdx.x < max_nb)
        idx[threadIdx.x] = agraph[a * max_nb + threadIdx.x];
    __syncthreads();

    const int AIN = atom_dim + H;
    float* out = ainput + a * AIN;
    for (int c = threadIdx.x; c < atom_dim; c += blockDim.x)
        out[c] = fatoms[a * atom_dim + c];
    for (int c = threadIdx.x; c < H; c += blockDim.x) {
        float s = 0.f;
        #pragma unroll 6
        for (int j = 0; j < max_nb; j++) s += __ldg(&msg[(long long)idx[j] * H + c]);
        out[atom_dim + c] = s;
    }
}

// ----------------------------------------------------------------------------
// Per-molecule mean over sorted mol_idx (binary search, no atomics).
// ----------------------------------------------------------------------------
__global__ __launch_bounds__(256)
void mol_mean(const int* __restrict__ mol_idx,
              float* __restrict__ out,
              int n_atoms, int H)
{
    const float* __restrict__ ah = g_ptrs[4];
    const int m = blockIdx.x;

    int l = 0, r = n_atoms;
    while (l < r) { int mid = (l + r) >> 1; if (mol_idx[mid] < m) l = mid + 1; else r = mid; }
    const int start = l;
    r = n_atoms;
    while (l < r) { int mid = (l + r) >> 1; if (mol_idx[mid] < m + 1) l = mid + 1; else r = mid; }
    const int end = l;
    const float inv = 1.f / fmaxf((float)(end - start), 1.f);

    for (int c = threadIdx.x; c < H; c += blockDim.x) {
        float s = 0.f;
        for (int a = start; a < end; a++) s += ah[(long long)a * H + c];
        out[(long long)m * H + c] = s * inv;
    }
}

// ----------------------------------------------------------------------------
// Launch — kernel launches ONLY (graph-capture safe, no runtime API calls).
// Scratch slots: 0=binput 1=msg 2=nei 3=ainput 4=ah
// ----------------------------------------------------------------------------
static inline dim3 gemm_grid(int M, int N) {
    return dim3((N + BN - 1) / BN, (M + BM - 1) / BM);
}

extern "C" void kernel_launch(void* const* d_in, const int* in_sizes, int n_in,
                              void* d_out, int out_size)
{
    const float* fatoms  = (const float*)d_in[0];
    const float* fbonds  = (const float*)d_in[1];
    const float* W_i     = (const float*)d_in[2];
    const float* W_h     = (const float*)d_in[3];
    const float* W_o     = (const float*)d_in[4];
    const float* b_o     = (const float*)d_in[5];
    const int*   agraph  = (const int*)d_in[6];      // int32 (JAX downgrades int64)
    const int*   bgraph  = (const int*)d_in[7];
    const int*   mol_idx = (const int*)d_in[8];

    const int n_atoms  = in_sizes[8];                 // mol_idx
    const int H        = in_sizes[5];                 // b_o
    const int BOND_IN  = in_sizes[2] / H;             // W_i: [BOND_IN, H]
    const int n_bonds  = in_sizes[1] / BOND_IN;       // fbonds
    const int ATOM_DIM = in_sizes[0] / n_atoms;       // fatoms
    const int MAX_NB   = in_sizes[6] / n_atoms;       // agraph
    const int n_mols   = out_size / H;
    const int AIN      = ATOM_DIM + H;

    init_ptrs<<<1, 32>>>();

    // 1. binput = fbonds @ W_i ; msg = relu(binput)
    gemm_f32<<<gemm_grid(n_bonds, H), 256>>>(
        fbonds, -1, BOND_IN, W_i,
        nullptr, -1, nullptr,
        nullptr, 0,            // Craw  -> binput
        nullptr, 1,            // Crelu -> msg
        n_bonds, H, BOND_IN);

    // 2. message passing: 4x (gather + GEMM + relu)
    for (int it = 0; it < DEPTH - 1; it++) {
        gather_bonds<<<(n_bonds + 1) / 2, 128>>>(bgraph, n_bonds, H, MAX_NB);
        gemm_f32<<<gemm_grid(n_bonds, H), 256>>>(
            nullptr, 2, H, W_h,   // A -> nei
            nullptr, 0, nullptr,  // C0 -> binput
            nullptr, -1,
            nullptr, 1,           // Crelu -> msg
            n_bonds, H, H);
    }

    // 3. atom readout
    build_ainput<<<n_atoms, 128>>>(fatoms, agraph, n_atoms, H, ATOM_DIM, MAX_NB);
    gemm_f32<<<gemm_grid(n_atoms, H), 256>>>(
        nullptr, 3, AIN, W_o,     // A -> ainput
        nullptr, -1, b_o,
        nullptr, -1,
        nullptr, 4,               // Crelu -> ah
        n_atoms, H, AIN);

    // 4. per-molecule mean pooling
    mol_mean<<<n_mols, 256>>>(mol_idx, (float*)d_out, n_atoms, H);
}

// round 4
// speedup vs baseline: 2.6116x; 2.6116x over previous
#include <cuda_runtime.h>
#include <cuda_bf16.h>
#include <cstdint>

// ----------------------------------------------------------------------------
// MPN (chemprop D-MPNN), round 4: tf32 tensor-core GEMM for depth loop + readout.
//   binput = fbonds @ W_i ; msg = relu(binput)                  [fp32 SIMT GEMM]
//   4x: nei = gather-sum(msg, bgraph) ; msg = relu(binput + nei @ W_h)  [tf32 MMA]
//   ainput=[fatoms|gather-sum(msg,agraph)|0pad] ; ah = relu(ainput@W_o + b_o) [tf32 MMA]
//   out[m] = mean over atoms of molecule m
// Index arrays are int32 (JAX downgrades int64). Scratch in __device__ globals.
// ----------------------------------------------------------------------------

#define DEPTH 5
#define AIN_PAD 496   // 486 padded to multiple of 16 (and 8-float alignment)

#define CAP_BONDxH 72000000ll   // >= 160001*448
#define CAP_ATOMxAIN 40000000ll // >= 80000*496 = 39,680,000
#define CAP_ATOMxH 36000000ll   // >= 80000*448

__device__ float g_binput[CAP_BONDxH];
__device__ float g_msg[CAP_BONDxH];
__device__ float g_nei[CAP_BONDxH];
__device__ float g_ainput[CAP_ATOMxAIN];
__device__ float g_ah[CAP_ATOMxH];

// slots: 0=binput 1=msg 2=nei 3=ainput 4=ah
__device__ float* g_ptrs[5];

__global__ void init_ptrs()
{
    if (threadIdx.x == 0) {
        g_ptrs[0] = g_binput;
        g_ptrs[1] = g_msg;
        g_ptrs[2] = g_nei;
        g_ptrs[3] = g_ainput;
        g_ptrs[4] = g_ah;
    }
}

__device__ __forceinline__ const float* resolve_c(const float* p, int slot) {
    return (slot >= 0) ? g_ptrs[slot] : p;
}
__device__ __forceinline__ float* resolve_m(float* p, int slot) {
    return (slot >= 0) ? g_ptrs[slot] : p;
}

// ============================================================================
// tf32 tensor-core GEMM
//   Out[M,N] = relu( A[M,K](lda, slot) @ B[Kreal,N] + C0 + bias )
// 128x128 block tile, BK=16, 256 threads (8 warps: 4 along M x 2 along N,
// each warp 32x64 = 2x8 m16n8k8 mma tiles). Double-buffered smem.
// A rows >= K columns valid (pad zeroed); B guarded with k < Kreal.
// ============================================================================
#define TBM 128
#define TBN 128
#define TBK 16
#define ASTR 20    // smem A row stride (16 + 4): conflict-free frag loads
#define BSTR 136   // smem B row stride (128 + 8): conflict-free frag loads

__device__ __forceinline__ uint32_t f2tf32(float x) {
    uint32_t r;
    asm("cvt.rna.tf32.f32 %0, %1;" : "=r"(r) : "f"(x));
    return r;
}

__device__ __forceinline__ void mma_tf32(float c[4],
                                         uint32_t a0, uint32_t a1, uint32_t a2, uint32_t a3,
                                         uint32_t b0, uint32_t b1)
{
    asm volatile(
        "mma.sync.aligned.m16n8k8.row.col.f32.tf32.tf32.f32 "
        "{%0,%1,%2,%3}, {%4,%5,%6,%7}, {%8,%9}, {%0,%1,%2,%3};\n"
        : "+f"(c[0]), "+f"(c[1]), "+f"(c[2]), "+f"(c[3])
        : "r"(a0), "r"(a1), "r"(a2), "r"(a3), "r"(b0), "r"(b1));
}

__global__ __launch_bounds__(256)
void gemm_tf32(int Aslot, int lda,
               const float* __restrict__ B,     // [Kreal, N] row-major
               int C0slot,                       // -1 = none
               const float* __restrict__ bias,   // [N] or null
               int OutSlot,
               int M, int N, int K, int Kreal)   // K = padded (mult of 16)
{
    const float* __restrict__ A  = g_ptrs[Aslot];
    const float* __restrict__ C0 = (C0slot >= 0) ? g_ptrs[C0slot] : nullptr;
    float* __restrict__ Out      = g_ptrs[OutSlot];

    __shared__ uint32_t As[2][TBM][ASTR];
    __shared__ uint32_t Bs[2][TBK][BSTR];

    const int tid = threadIdx.x;
    const int bm = blockIdx.y * TBM;
    const int bn = blockIdx.x * TBN;

    const int wid  = tid >> 5;
    const int lane = tid & 31;
    const int wm = (wid & 3) * 32;   // warp M offset in tile
    const int wn = (wid >> 2) * 64;  // warp N offset in tile
    const int g   = lane >> 2;       // groupID 0..7
    const int tig = lane & 3;        // threadID_in_group 0..3

    // gmem->reg staging maps
    // A: 128 rows x 16 cols -> 512 float4; thread handles f = tid, tid+256
    // B: 16 rows x 128 cols -> 512 float4
    float4 rA[2], rB[2];

    const int nk = K / TBK;

    auto ldg_tile = [&](int t) {
        const int k0 = t * TBK;
        #pragma unroll
        for (int i = 0; i < 2; i++) {
            int f = tid + i * 256;
            int ar = f >> 2, ac = (f & 3) * 4;
            int grow = bm + ar;
            if (grow < M)
                rA[i] = *(const float4*)&A[(long long)grow * lda + k0 + ac];
            else
                rA[i] = make_float4(0.f, 0.f, 0.f, 0.f);

            int brr = f >> 5, bcc = (f & 31) * 4;
            int gk = k0 + brr, gn = bn + bcc;
            if (gk < Kreal && gn < N)
                rB[i] = *(const float4*)&B[(long long)gk * N + gn];
            else
                rB[i] = make_float4(0.f, 0.f, 0.f, 0.f);
        }
    };

    auto sts_tile = [&](int buf) {
        #pragma unroll
        for (int i = 0; i < 2; i++) {
            int f = tid + i * 256;
            int ar = f >> 2, ac = (f & 3) * 4;
            uint4 va;
            va.x = f2tf32(rA[i].x); va.y = f2tf32(rA[i].y);
            va.z = f2tf32(rA[i].z); va.w = f2tf32(rA[i].w);
            *(uint4*)&As[buf][ar][ac] = va;

            int brr = f >> 5, bcc = (f & 31) * 4;
            uint4 vb;
            vb.x = f2tf32(rB[i].x); vb.y = f2tf32(rB[i].y);
            vb.z = f2tf32(rB[i].z); vb.w = f2tf32(rB[i].w);
            *(uint4*)&Bs[buf][brr][bcc] = vb;
        }
    };

    float acc[2][8][4];
    #pragma unroll
    for (int mt = 0; mt < 2; mt++)
        #pragma unroll
        for (int nt = 0; nt < 8; nt++)
            #pragma unroll
            for (int r = 0; r < 4; r++) acc[mt][nt][r] = 0.f;

    // prologue
    ldg_tile(0);
    sts_tile(0);
    if (nk > 1) ldg_tile(1);
    __syncthreads();

    for (int t = 0; t < nk; t++) {
        const int buf = t & 1;
        // compute tile t
        #pragma unroll
        for (int kk = 0; kk < TBK; kk += 8) {
            uint32_t a[2][4];
            #pragma unroll
            for (int mt = 0; mt < 2; mt++) {
                int m0 = wm + mt * 16;
                a[mt][0] = As[buf][m0 + g    ][kk + tig];
                a[mt][1] = As[buf][m0 + g + 8][kk + tig];
                a[mt][2] = As[buf][m0 + g    ][kk + tig + 4];
                a[mt][3] = As[buf][m0 + g + 8][kk + tig + 4];
            }
            uint32_t b[8][2];
            #pragma unroll
            for (int nt = 0; nt < 8; nt++) {
                int n0 = wn + nt * 8;
                b[nt][0] = Bs[buf][kk + tig    ][n0 + g];
                b[nt][1] = Bs[buf][kk + tig + 4][n0 + g];
            }
            #pragma unroll
            for (int mt = 0; mt < 2; mt++)
                #pragma unroll
                for (int nt = 0; nt < 8; nt++)
                    mma_tf32(acc[mt][nt], a[mt][0], a[mt][1], a[mt][2], a[mt][3],
                             b[nt][0], b[nt][1]);
        }
        __syncthreads();
        if (t + 1 < nk) {
            sts_tile((t + 1) & 1);
            if (t + 2 < nk) ldg_tile(t + 2);
            __syncthreads();
        }
    }

    // epilogue: c0,c1 -> (row g, cols 2tig,2tig+1); c2,c3 -> (row g+8)
    #pragma unroll
    for (int mt = 0; mt < 2; mt++) {
        #pragma unroll
        for (int nt = 0; nt < 8; nt++) {
            int col = bn + wn + nt * 8 + tig * 2;
            if (col >= N) continue;
            #pragma unroll
            for (int h = 0; h < 2; h++) {
                int row = bm + wm + mt * 16 + g + h * 8;
                if (row >= M) continue;
                long long o = (long long)row * N + col;
                float v0 = acc[mt][nt][h * 2 + 0];
                float v1 = acc[mt][nt][h * 2 + 1];
                if (C0)   { v0 += C0[o];   v1 += C0[o + 1]; }
                if (bias) { v0 += bias[col]; v1 += bias[col + 1]; }
                float2 w = make_float2(fmaxf(v0, 0.f), fmaxf(v1, 0.f));
                *(float2*)&Out[o] = w;
            }
        }
    }
}

// ============================================================================
// fp32 SIMT GEMM (kept for binput: K=49, memory-bound, full precision)
// ============================================================================
#define BM 128
#define BN 128
#define BKK 8
#define TM 8
#define TN 8

__global__ __launch_bounds__(256)
void gemm_f32(const float* Ax, int Aslot, int lda,
              const float* __restrict__ B,
              const float* C0x, int C0slot,
              const float* __restrict__ bias,
              float* Crawx, int Crawslot,
              float* Crelux, int Creluslot,
              int M, int N, int K)
{
    const float* __restrict__ A  = resolve_c(Ax, Aslot);
    const float* __restrict__ C0 = resolve_c(C0x, C0slot);
    float* __restrict__ Craw  = resolve_m(Crawx, Crawslot);
    float* __restrict__ Crelu = resolve_m(Crelux, Creluslot);

    __shared__ float As[BKK][BM];
    __shared__ float Bs[BKK][BN];

    const int tid = threadIdx.x;
    const int bm = blockIdx.y * BM;
    const int bn = blockIdx.x * BN;
    const int tx = tid & 15;
    const int ty = tid >> 4;
    const int ar = tid >> 1;
    const int ac = (tid & 1) * 4;
    const int br = tid >> 5;
    const int bc = (tid & 31) * 4;

    float acc[TM][TN];
    #pragma unroll
    for (int i = 0; i < TM; i++)
        #pragma unroll
        for (int j = 0; j < TN; j++) acc[i][j] = 0.f;

    for (int k0 = 0; k0 < K; k0 += BKK) {
        {
            long long row = (long long)(bm + ar);
            const bool rok = (bm + ar) < M;
            #pragma unroll
            for (int j = 0; j < 4; j++) {
                int k = k0 + ac + j;
                float v = 0.f;
                if (rok && k < K) v = A[row * lda + k];
                As[ac + j][ar] = v;
            }
        }
        {
            int k = k0 + br;
            float4 v = make_float4(0.f, 0.f, 0.f, 0.f);
            if (k < K) {
                if (bn + bc + 3 < N) {
                    v = *(const float4*)&B[(long long)k * N + bn + bc];
                } else {
                    float* pv = (float*)&v;
                    #pragma unroll
                    for (int j = 0; j < 4; j++) {
                        int n = bn + bc + j;
                        pv[j] = (n < N) ? B[(long long)k * N + n] : 0.f;
                    }
                }
            }
            *(float4*)&Bs[br][bc] = v;
        }
        __syncthreads();

        #pragma unroll
        for (int kk = 0; kk < BKK; kk++) {
            float a[TM], b[TN];
            #pragma unroll
            for (int i = 0; i < TM; i++) a[i] = As[kk][ty * TM + i];
            #pragma unroll
            for (int j = 0; j < TN; j++) b[j] = Bs[kk][tx * TN + j];
            #pragma unroll
            for (int i = 0; i < TM; i++)
                #pragma unroll
                for (int j = 0; j < TN; j++)
                    acc[i][j] += a[i] * b[j];
        }
        __syncthreads();
    }

    #pragma unroll
    for (int i = 0; i < TM; i++) {
        int mi = bm + ty * TM + i;
        if (mi >= M) continue;
        long long mrow = (long long)mi * N;
        #pragma unroll
        for (int j = 0; j < TN; j++) {
            int n = bn + tx * TN + j;
            if (n >= N) continue;
            float v = acc[i][j];
            if (C0)   v += C0[mrow + n];
            if (bias) v += bias[n];
            if (Craw)  Craw[mrow + n] = v;
            if (Crelu) Crelu[mrow + n] = fmaxf(v, 0.f);
        }
    }
}

// ----------------------------------------------------------------------------
// Bond neighbor gather-sum: nei[b] = sum_j msg[bgraph[b][j]]
// ----------------------------------------------------------------------------
__global__ __launch_bounds__(128)
void gather_bonds(const int* __restrict__ bgraph,
                  int n_bonds, int H, int max_nb)
{
    const float* __restrict__ msg = g_ptrs[1];
    float* __restrict__ nei       = g_ptrs[2];

    const int half = threadIdx.x >> 6;
    const int lane = threadIdx.x & 63;
    const long long b = (long long)blockIdx.x * 2 + half;
    const bool valid = (b < n_bonds);

    __shared__ int idx[2][8];
    if (valid && lane < max_nb)
        idx[half][lane] = bgraph[b * max_nb + lane];
    __syncthreads();
    if (!valid) return;

    const int H4 = H >> 2;
    for (int c = lane; c < H4; c += 64) {
        float4 s = make_float4(0.f, 0.f, 0.f, 0.f);
        #pragma unroll 6
        for (int j = 0; j < max_nb; j++) {
            const float4 v = __ldg((const float4*)&msg[(long long)idx[half][j] * H + c * 4]);
            s.x += v.x; s.y += v.y; s.z += v.z; s.w += v.w;
        }
        *(float4*)&nei[b * H + c * 4] = s;
    }
    for (int c = H4 * 4 + lane; c < H; c += 64) {
        float s = 0.f;
        for (int j = 0; j < max_nb; j++) s += msg[(long long)idx[half][j] * H + c];
        nei[b * H + c] = s;
    }
}

// ----------------------------------------------------------------------------
// ainput[a] = [ fatoms[a] | sum_j msg[agraph[a][j]] | zero pad ]  (stride AIN_PAD)
// ----------------------------------------------------------------------------
__global__ __launch_bounds__(128)
void build_ainput(const float* __restrict__ fatoms,
                  const int* __restrict__ agraph,
                  int n_atoms, int H, int atom_dim, int max_nb)
{
    const float* __restrict__ msg = g_ptrs[1];
    float* __restrict__ ainput    = g_ptrs[3];

    const long long a = blockIdx.x;
    __shared__ int idx[8];
    if (threadIdx.x < max_nb)
        idx[threadIdx.x] = agraph[a * max_nb + threadIdx.x];
    __syncthreads();

    const int AIN = atom_dim + H;
    float* out = ainput + a * AIN_PAD;
    for (int c = threadIdx.x; c < atom_dim; c += blockDim.x)
        out[c] = fatoms[a * atom_dim + c];
    for (int c = threadIdx.x; c < H; c += blockDim.x) {
        float s = 0.f;
        #pragma unroll 6
        for (int j = 0; j < max_nb; j++) s += __ldg(&msg[(long long)idx[j] * H + c]);
        out[atom_dim + c] = s;
    }
    for (int c = AIN + threadIdx.x; c < AIN_PAD; c += blockDim.x)
        out[c] = 0.f;
}

// ----------------------------------------------------------------------------
// Per-molecule mean over sorted mol_idx (binary search, no atomics).
// ----------------------------------------------------------------------------
__global__ __launch_bounds__(256)
void mol_mean(const int* __restrict__ mol_idx,
              float* __restrict__ out,
              int n_atoms, int H)
{
    const float* __restrict__ ah = g_ptrs[4];
    const int m = blockIdx.x;

    int l = 0, r = n_atoms;
    while (l < r) { int mid = (l + r) >> 1; if (mol_idx[mid] < m) l = mid + 1; else r = mid; }
    const int start = l;
    r = n_atoms;
    while (l < r) { int mid = (l + r) >> 1; if (mol_idx[mid] < m + 1) l = mid + 1; else r = mid; }
    const int end = l;
    const float inv = 1.f / fmaxf((float)(end - start), 1.f);

    for (int c = threadIdx.x; c < H; c += blockDim.x) {
        float s = 0.f;
        for (int a = start; a < end; a++) s += ah[(long long)a * H + c];
        out[(long long)m * H + c] = s * inv;
    }
}

// ----------------------------------------------------------------------------
// Launch — kernel launches only.
// ----------------------------------------------------------------------------
static inline dim3 g128(int M, int N) {
    return dim3((N + 127) / 128, (M + 127) / 128);
}

extern "C" void kernel_launch(void* const* d_in, const int* in_sizes, int n_in,
                              void* d_out, int out_size)
{
    const float* fatoms  = (const float*)d_in[0];
    const float* fbonds  = (const float*)d_in[1];
    const float* W_i     = (const float*)d_in[2];
    const float* W_h     = (const float*)d_in[3];
    const float* W_o     = (const float*)d_in[4];
    const float* b_o     = (const float*)d_in[5];
    const int*   agraph  = (const int*)d_in[6];
    const int*   bgraph  = (const int*)d_in[7];
    const int*   mol_idx = (const int*)d_in[8];

    const int n_atoms  = in_sizes[8];
    const int H        = in_sizes[5];
    const int BOND_IN  = in_sizes[2] / H;
    const int n_bonds  = in_sizes[1] / BOND_IN;
    const int ATOM_DIM = in_sizes[0] / n_atoms;
    const int MAX_NB   = in_sizes[6] / n_atoms;
    const int n_mols   = out_size / H;
    const int AIN      = ATOM_DIM + H;   // 486

    init_ptrs<<<1, 32>>>();

    // 1. binput = fbonds @ W_i ; msg = relu(binput)   [fp32]
    gemm_f32<<<g128(n_bonds, H), 256>>>(
        fbonds, -1, BOND_IN, W_i,
        nullptr, -1, nullptr,
        nullptr, 0,            // Craw  -> binput
        nullptr, 1,            // Crelu -> msg
        n_bonds, H, BOND_IN);

    // 2. message passing: 4x (gather + tf32 GEMM)
    for (int it = 0; it < DEPTH - 1; it++) {
        gather_bonds<<<(n_bonds + 1) / 2, 128>>>(bgraph, n_bonds, H, MAX_NB);
        gemm_tf32<<<g128(n_bonds, H), 256>>>(
            /*Aslot*/2, /*lda*/H, W_h,
            /*C0slot*/0, /*bias*/nullptr,
            /*OutSlot*/1,
            n_bonds, H, H, H);
    }

    // 3. atom readout (K padded to AIN_PAD, pad zeroed in build_ainput)
    build_ainput<<<n_atoms, 128>>>(fatoms, agraph, n_atoms, H, ATOM_DIM, MAX_NB);
    gemm_tf32<<<g128(n_atoms, H), 256>>>(
        /*Aslot*/3, /*lda*/AIN_PAD, W_o,
        /*C0slot*/-1, /*bias*/b_o,
        /*OutSlot*/4,
        n_atoms, H, AIN_PAD, AIN);

    // 4. per-molecule mean pooling
    mol_mean<<<n_mols, 256>>>(mol_idx, (float*)d_out, n_atoms, H);
}

// round 5
// speedup vs baseline: 2.8348x; 1.0855x over previous
#include <cuda_runtime.h>
#include <cuda_bf16.h>
#include <cstdint>

// ----------------------------------------------------------------------------
// MPN (chemprop D-MPNN), round 5: cp.async multistage tf32 tensor-core GEMM.
// tf32 conversion moved to producers (gather/build_ainput/weight-convert), so
// the GEMM pipeline is a pure async copy + mma machine.
// Index arrays are int32 (JAX downgrades int64). Scratch in __device__ globals.
// ----------------------------------------------------------------------------

#define DEPTH 5
#define AIN_PAD 496   // 486 padded to multiple of 16

#define CAP_BONDxH 72000000ll
#define CAP_ATOMxAIN 40000000ll
#define CAP_ATOMxH 36000000ll
#define CAP_WH 201000     // 448*448
#define CAP_WO 218000     // 486*448

__device__ float g_binput[CAP_BONDxH];
__device__ float g_msg[CAP_BONDxH];
__device__ float g_nei[CAP_BONDxH];
__device__ float g_ainput[CAP_ATOMxAIN];
__device__ float g_ah[CAP_ATOMxH];
__device__ float g_Wh[CAP_WH];
__device__ float g_Wo[CAP_WO];

// slots: 0=binput 1=msg 2=nei 3=ainput 4=ah 5=Wh(tf32) 6=Wo(tf32)
__device__ float* g_ptrs[7];

__global__ void init_ptrs()
{
    if (threadIdx.x == 0) {
        g_ptrs[0] = g_binput;
        g_ptrs[1] = g_msg;
        g_ptrs[2] = g_nei;
        g_ptrs[3] = g_ainput;
        g_ptrs[4] = g_ah;
        g_ptrs[5] = g_Wh;
        g_ptrs[6] = g_Wo;
    }
}

__device__ __forceinline__ uint32_t f2tf32(float x) {
    uint32_t r;
    asm("cvt.rna.tf32.f32 %0, %1;" : "=r"(r) : "f"(x));
    return r;
}
__device__ __forceinline__ float f2tf32f(float x) {
    return __uint_as_float(f2tf32(x));
}

// One-shot: round W_h and W_o to tf32 into scratch (cheap, memory-bound).
__global__ void cvt_weights(const float* __restrict__ Wh, int nh,
                            const float* __restrict__ Wo, int no)
{
    float* dWh = g_ptrs[5];
    float* dWo = g_ptrs[6];
    for (int i = blockIdx.x * blockDim.x + threadIdx.x; i < nh + no;
         i += gridDim.x * blockDim.x) {
        if (i < nh) dWh[i] = f2tf32f(Wh[i]);
        else        dWo[i - nh] = f2tf32f(Wo[i - nh]);
    }
}

// ============================================================================
// tf32 tensor-core GEMM, cp.async 4-stage pipeline.
//   Out[M,N] = relu( A[M,K](slot, lda) @ B[Kreal,N](slot) + C0(slot) + bias )
// 128x128 tile, BK=16, 256 threads (8 warps, 32x64 warp tile, m16n8k8).
// A/B smem data must already be tf32-rounded fp32 bits.
// ============================================================================
#define TBM 128
#define TBN 128
#define TBK 16
#define ASTR 20          // A smem row stride (words): conflict-free frags
#define BSTR 132         // B smem row stride (words): conflict-free frags
#define A_WORDS (TBM * ASTR)            // 2560
#define B_WORDS (TBK * BSTR)            // 2112
#define STAGE_WORDS (A_WORDS + B_WORDS) // 4672
#define NSTAGE 4
#define GEMM_SMEM_BYTES (NSTAGE * STAGE_WORDS * 4)  // 74752

__device__ __forceinline__ void cp16(void* sdst, const void* gsrc, bool p) {
    uint32_t d = (uint32_t)__cvta_generic_to_shared(sdst);
    int sz = p ? 16 : 0;
    asm volatile("cp.async.cg.shared.global [%0], [%1], 16, %2;\n"
                 :: "r"(d), "l"(gsrc), "r"(sz));
}
__device__ __forceinline__ void cp_commit() {
    asm volatile("cp.async.commit_group;\n");
}
template<int NN> __device__ __forceinline__ void cp_wait() {
    asm volatile("cp.async.wait_group %0;\n" :: "n"(NN));
}

__device__ __forceinline__ void mma_tf32(float c[4],
                                         uint32_t a0, uint32_t a1, uint32_t a2, uint32_t a3,
                                         uint32_t b0, uint32_t b1)
{
    asm volatile(
        "mma.sync.aligned.m16n8k8.row.col.f32.tf32.tf32.f32 "
        "{%0,%1,%2,%3}, {%4,%5,%6,%7}, {%8,%9}, {%0,%1,%2,%3};\n"
        : "+f"(c[0]), "+f"(c[1]), "+f"(c[2]), "+f"(c[3])
        : "r"(a0), "r"(a1), "r"(a2), "r"(a3), "r"(b0), "r"(b1));
}

extern __shared__ uint32_t smem_u[];

__global__ __launch_bounds__(256)
void gemm_tf32(int Aslot, int lda,
               int Bslot,                        // [Kreal, N] row-major, tf32 bits
               int C0slot,                       // -1 = none
               const float* __restrict__ bias,   // [N] or null
               int OutSlot,
               int M, int N, int K, int Kreal)   // K padded (mult of TBK), nk >= NSTAGE
{
    const float* __restrict__ A  = g_ptrs[Aslot];
    const float* __restrict__ B  = g_ptrs[Bslot];
    const float* __restrict__ C0 = (C0slot >= 0) ? g_ptrs[C0slot] : nullptr;
    float* __restrict__ Out      = g_ptrs[OutSlot];

    const int tid = threadIdx.x;
    const int bm = blockIdx.y * TBM;
    const int bn = blockIdx.x * TBN;

    const int wid  = tid >> 5;
    const int lane = tid & 31;
    const int wm = (wid & 3) * 32;
    const int wn = (wid >> 2) * 64;
    const int g   = lane >> 2;
    const int tig = lane & 3;

    // copy maps (per thread: 2 A float4 + 2 B float4 per stage)
    const int ar = tid >> 2;            // A rows: f=tid -> ar, f=tid+256 -> ar+64
    const int ac = (tid & 3) * 4;
    const int brr = tid >> 6;           // B rows: brr, brr+4, (f+256 -> +8?) see below
    const int bcc = (tid & 63) * 4;     // wait: 64 threads cover 256 cols? no.

    // B tile is 16 x 128 floats = 512 float4; map f=tid(+256): row f>>5, col (f&31)*4
    const int nk = K / TBK;

    auto issue = [&](int t) {
        const int s = t % NSTAGE;
        uint32_t* As = smem_u + s * STAGE_WORDS;
        uint32_t* Bs = As + A_WORDS;
        const int k0 = t * TBK;
        #pragma unroll
        for (int i = 0; i < 2; i++) {
            // A
            int arow = ar + i * 64;
            int grow = bm + arow;
            bool pa = (grow < M);
            const float* srcA = &A[(long long)(pa ? grow : 0) * lda + k0 + ac];
            cp16(&As[arow * ASTR + ac], srcA, pa);
            // B
            int f = tid + i * 256;
            int br_ = f >> 5;
            int bc_ = (f & 31) * 4;
            int gk = k0 + br_, gn = bn + bc_;
            bool pb = (gk < Kreal) && (gn < N);
            const float* srcB = &B[(long long)(pb ? gk : 0) * N + (pb ? gn : 0)];
            cp16(&Bs[br_ * BSTR + bc_], srcB, pb);
        }
    };

    float acc[2][8][4];
    #pragma unroll
    for (int mt = 0; mt < 2; mt++)
        #pragma unroll
        for (int nt = 0; nt < 8; nt++)
            #pragma unroll
            for (int r = 0; r < 4; r++) acc[mt][nt][r] = 0.f;

    // prologue: fill NSTAGE-1 stages
    #pragma unroll
    for (int t = 0; t < NSTAGE - 1; t++) { issue(t); cp_commit(); }
    cp_wait<NSTAGE - 2>();
    __syncthreads();

    for (int t = 0; t < nk; t++) {
        const uint32_t* As = smem_u + (t % NSTAGE) * STAGE_WORDS;
        const uint32_t* Bs = As + A_WORDS;

        #pragma unroll
        for (int kk = 0; kk < TBK; kk += 8) {
            uint32_t a[2][4];
            #pragma unroll
            for (int mt = 0; mt < 2; mt++) {
                int m0 = wm + mt * 16;
                a[mt][0] = As[(m0 + g    ) * ASTR + kk + tig];
                a[mt][1] = As[(m0 + g + 8) * ASTR + kk + tig];
                a[mt][2] = As[(m0 + g    ) * ASTR + kk + tig + 4];
                a[mt][3] = As[(m0 + g + 8) * ASTR + kk + tig + 4];
            }
            uint32_t b[8][2];
            #pragma unroll
            for (int nt = 0; nt < 8; nt++) {
                int n0 = wn + nt * 8;
                b[nt][0] = Bs[(kk + tig    ) * BSTR + n0 + g];
                b[nt][1] = Bs[(kk + tig + 4) * BSTR + n0 + g];
            }
            #pragma unroll
            for (int mt = 0; mt < 2; mt++)
                #pragma unroll
                for (int nt = 0; nt < 8; nt++)
                    mma_tf32(acc[mt][nt], a[mt][0], a[mt][1], a[mt][2], a[mt][3],
                             b[nt][0], b[nt][1]);
        }

        if (t + NSTAGE - 1 < nk) issue(t + NSTAGE - 1);
        cp_commit();
        cp_wait<NSTAGE - 2>();
        __syncthreads();
    }

    // epilogue
    #pragma unroll
    for (int mt = 0; mt < 2; mt++) {
        #pragma unroll
        for (int nt = 0; nt < 8; nt++) {
            int col = bn + wn + nt * 8 + tig * 2;
            if (col >= N) continue;
            #pragma unroll
            for (int h = 0; h < 2; h++) {
                int row = bm + wm + mt * 16 + g + h * 8;
                if (row >= M) continue;
                long long o = (long long)row * N + col;
                float v0 = acc[mt][nt][h * 2 + 0];
                float v1 = acc[mt][nt][h * 2 + 1];
                if (C0)   { v0 += C0[o];     v1 += C0[o + 1]; }
                if (bias) { v0 += bias[col]; v1 += bias[col + 1]; }
                *(float2*)&Out[o] = make_float2(fmaxf(v0, 0.f), fmaxf(v1, 0.f));
            }
        }
    }
}

// ============================================================================
// fp32 SIMT GEMM (binput: K=49, memory-bound, full precision)
// ============================================================================
#define BM 128
#define BN 128
#define BKK 8
#define TM 8
#define TN 8

__global__ __launch_bounds__(256)
void gemm_f32(const float* __restrict__ A, int lda,
              const float* __restrict__ B,
              int CrawSlot, int CreluSlot,
              int M, int N, int K)
{
    float* __restrict__ Craw  = g_ptrs[CrawSlot];
    float* __restrict__ Crelu = g_ptrs[CreluSlot];

    __shared__ float As[BKK][BM];
    __shared__ float Bs[BKK][BN];

    const int tid = threadIdx.x;
    const int bm = blockIdx.y * BM;
    const int bn = blockIdx.x * BN;
    const int tx = tid & 15;
    const int ty = tid >> 4;
    const int ar = tid >> 1;
    const int ac = (tid & 1) * 4;
    const int br = tid >> 5;
    const int bc = (tid & 31) * 4;

    float acc[TM][TN];
    #pragma unroll
    for (int i = 0; i < TM; i++)
        #pragma unroll
        for (int j = 0; j < TN; j++) acc[i][j] = 0.f;

    for (int k0 = 0; k0 < K; k0 += BKK) {
        {
            long long row = (long long)(bm + ar);
            const bool rok = (bm + ar) < M;
            #pragma unroll
            for (int j = 0; j < 4; j++) {
                int k = k0 + ac + j;
                float v = 0.f;
                if (rok && k < K) v = A[row * lda + k];
                As[ac + j][ar] = v;
            }
        }
        {
            int k = k0 + br;
            float4 v = make_float4(0.f, 0.f, 0.f, 0.f);
            if (k < K) {
                if (bn + bc + 3 < N) {
                    v = *(const float4*)&B[(long long)k * N + bn + bc];
                } else {
                    float* pv = (float*)&v;
                    #pragma unroll
                    for (int j = 0; j < 4; j++) {
                        int n = bn + bc + j;
                        pv[j] = (n < N) ? B[(long long)k * N + n] : 0.f;
                    }
                }
            }
            *(float4*)&Bs[br][bc] = v;
        }
        __syncthreads();

        #pragma unroll
        for (int kk = 0; kk < BKK; kk++) {
            float a[TM], b[TN];
            #pragma unroll
            for (int i = 0; i < TM; i++) a[i] = As[kk][ty * TM + i];
            #pragma unroll
            for (int j = 0; j < TN; j++) b[j] = Bs[kk][tx * TN + j];
            #pragma unroll
            for (int i = 0; i < TM; i++)
                #pragma unroll
                for (int j = 0; j < TN; j++)
                    acc[i][j] += a[i] * b[j];
        }
        __syncthreads();
    }

    #pragma unroll
    for (int i = 0; i < TM; i++) {
        int mi = bm + ty * TM + i;
        if (mi >= M) continue;
        long long mrow = (long long)mi * N;
        #pragma unroll
        for (int j = 0; j < TN; j++) {
            int n = bn + tx * TN + j;
            if (n >= N) continue;
            float v = acc[i][j];
            Craw[mrow + n] = v;
            Crelu[mrow + n] = fmaxf(v, 0.f);
        }
    }
}

// ----------------------------------------------------------------------------
// Bond gather-sum: nei[b] = tf32_round( sum_j msg[bgraph[b][j]] )
// ----------------------------------------------------------------------------
__global__ __launch_bounds__(128)
void gather_bonds(const int* __restrict__ bgraph,
                  int n_bonds, int H, int max_nb)
{
    const float* __restrict__ msg = g_ptrs[1];
    float* __restrict__ nei       = g_ptrs[2];

    const int half = threadIdx.x >> 6;
    const int lane = threadIdx.x & 63;
    const long long b = (long long)blockIdx.x * 2 + half;
    const bool valid = (b < n_bonds);

    __shared__ int idx[2][8];
    if (valid && lane < max_nb)
        idx[half][lane] = bgraph[b * max_nb + lane];
    __syncthreads();
    if (!valid) return;

    const int H4 = H >> 2;
    for (int c = lane; c < H4; c += 64) {
        float4 s = make_float4(0.f, 0.f, 0.f, 0.f);
        #pragma unroll 6
        for (int j = 0; j < max_nb; j++) {
            const float4 v = __ldg((const float4*)&msg[(long long)idx[half][j] * H + c * 4]);
            s.x += v.x; s.y += v.y; s.z += v.z; s.w += v.w;
        }
        s.x = f2tf32f(s.x); s.y = f2tf32f(s.y);
        s.z = f2tf32f(s.z); s.w = f2tf32f(s.w);
        *(float4*)&nei[b * H + c * 4] = s;
    }
    for (int c = H4 * 4 + lane; c < H; c += 64) {
        float s = 0.f;
        for (int j = 0; j < max_nb; j++) s += msg[(long long)idx[half][j] * H + c];
        nei[b * H + c] = f2tf32f(s);
    }
}

// ----------------------------------------------------------------------------
// ainput[a] = tf32_round([ fatoms[a] | sum_j msg[agraph[a][j]] | 0 pad ])
// ----------------------------------------------------------------------------
__global__ __launch_bounds__(128)
void build_ainput(const float* __restrict__ fatoms,
                  const int* __restrict__ agraph,
                  int n_atoms, int H, int atom_dim, int max_nb)
{
    const float* __restrict__ msg = g_ptrs[1];
    float* __restrict__ ainput    = g_ptrs[3];

    const long long a = blockIdx.x;
    __shared__ int idx[8];
    if (threadIdx.x < max_nb)
        idx[threadIdx.x] = agraph[a * max_nb + threadIdx.x];
    __syncthreads();

    const int AIN = atom_dim + H;
    float* out = ainput + a * AIN_PAD;
    for (int c = threadIdx.x; c < atom_dim; c += blockDim.x)
        out[c] = f2tf32f(fatoms[a * atom_dim + c]);
    for (int c = threadIdx.x; c < H; c += blockDim.x) {
        float s = 0.f;
        #pragma unroll 6
        for (int j = 0; j < max_nb; j++) s += __ldg(&msg[(long long)idx[j] * H + c]);
        out[atom_dim + c] = f2tf32f(s);
    }
    for (int c = AIN + threadIdx.x; c < AIN_PAD; c += blockDim.x)
        out[c] = 0.f;
}

// ----------------------------------------------------------------------------
// Per-molecule mean over sorted mol_idx.
// ----------------------------------------------------------------------------
__global__ __launch_bounds__(256)
void mol_mean(const int* __restrict__ mol_idx,
              float* __restrict__ out,
              int n_atoms, int H)
{
    const float* __restrict__ ah = g_ptrs[4];
    const int m = blockIdx.x;

    int l = 0, r = n_atoms;
    while (l < r) { int mid = (l + r) >> 1; if (mol_idx[mid] < m) l = mid + 1; else r = mid; }
    const int start = l;
    r = n_atoms;
    while (l < r) { int mid = (l + r) >> 1; if (mol_idx[mid] < m + 1) l = mid + 1; else r = mid; }
    const int end = l;
    const float inv = 1.f / fmaxf((float)(end - start), 1.f);

    for (int c = threadIdx.x; c < H; c += blockDim.x) {
        float s = 0.f;
        for (int a = start; a < end; a++) s += ah[(long long)a * H + c];
        out[(long long)m * H + c] = s * inv;
    }
}

// ----------------------------------------------------------------------------
// Launch
// ----------------------------------------------------------------------------
static inline dim3 g128(int M, int N) {
    return dim3((N + 127) / 128, (M + 127) / 128);
}

extern "C" void kernel_launch(void* const* d_in, const int* in_sizes, int n_in,
                              void* d_out, int out_size)
{
    const float* fatoms  = (const float*)d_in[0];
    const float* fbonds  = (const float*)d_in[1];
    const float* W_i     = (const float*)d_in[2];
    const float* W_h     = (const float*)d_in[3];
    const float* W_o     = (const float*)d_in[4];
    const float* b_o     = (const float*)d_in[5];
    const int*   agraph  = (const int*)d_in[6];
    const int*   bgraph  = (const int*)d_in[7];
    const int*   mol_idx = (const int*)d_in[8];

    const int n_atoms  = in_sizes[8];
    const int H        = in_sizes[5];
    const int BOND_IN  = in_sizes[2] / H;
    const int n_bonds  = in_sizes[1] / BOND_IN;
    const int ATOM_DIM = in_sizes[0] / n_atoms;
    const int MAX_NB   = in_sizes[6] / n_atoms;
    const int n_mols   = out_size / H;
    const int AIN      = ATOM_DIM + H;   // 486

    cudaFuncSetAttribute(gemm_tf32, cudaFuncAttributeMaxDynamicSharedMemorySize,
                         GEMM_SMEM_BYTES);

    init_ptrs<<<1, 32>>>();
    cvt_weights<<<256, 256>>>(W_h, H * H, W_o, AIN * H);

    // 1. binput = fbonds @ W_i ; msg = relu(binput)   [fp32]
    gemm_f32<<<g128(n_bonds, H), 256>>>(
        fbonds, BOND_IN, W_i,
        /*Craw*/0, /*Crelu*/1,
        n_bonds, H, BOND_IN);

    // 2. message passing: 4x (gather + tf32 GEMM)
    for (int it = 0; it < DEPTH - 1; it++) {
        gather_bonds<<<(n_bonds + 1) / 2, 128>>>(bgraph, n_bonds, H, MAX_NB);
        gemm_tf32<<<g128(n_bonds, H), 256, GEMM_SMEM_BYTES>>>(
            /*Aslot*/2, /*lda*/H, /*Bslot*/5,
            /*C0slot*/0, /*bias*/nullptr, /*OutSlot*/1,
            n_bonds, H, H, H);
    }

    // 3. atom readout
    build_ainput<<<n_atoms, 128>>>(fatoms, agraph, n_atoms, H, ATOM_DIM, MAX_NB);
    gemm_tf32<<<g128(n_atoms, H), 256, GEMM_SMEM_BYTES>>>(
        /*Aslot*/3, /*lda*/AIN_PAD, /*Bslot*/6,
        /*C0slot*/-1, /*bias*/b_o, /*OutSlot*/4,
        n_atoms, H, AIN_PAD, AIN);

    // 4. per-molecule mean pooling
    mol_mean<<<n_mols, 256>>>(mol_idx, (float*)d_out, n_atoms, H);
}

// round 6
// speedup vs baseline: 3.3023x; 1.1649x over previous
#include <cuda_runtime.h>
#include <cuda_fp16.h>
#include <cstdint>

// ----------------------------------------------------------------------------
// MPN (chemprop D-MPNN), round 6:
//   Factor gather through the GEMM:  Σ_j msg[idx_j] @ W_h  ==  Σ_j (msg@W_h)[idx_j]
//   -> depth iter = dense GEMM (msgW = msg@Wh, fp16 out) + fused
//      gather/add/relu (msg = tf32(relu(binput + Σ msgW[idx_j]))).
//   nei buffer eliminated; msgW in fp16 (same mantissa as tf32) halves gather
//   traffic and makes it ~L2-resident.
// Index arrays are int32 (JAX downgrades int64). Scratch in __device__ globals.
// ----------------------------------------------------------------------------

#define DEPTH 5
#define AIN_PAD 496   // 486 padded to multiple of 16

#define CAP_BONDxH 72000000ll
#define CAP_ATOMxAIN 40000000ll
#define CAP_ATOMxH 36000000ll
#define CAP_WH 201000     // 448*448
#define CAP_WO 218000     // 486*448

__device__ float g_binput[CAP_BONDxH];
__device__ float g_msg[CAP_BONDxH];
__device__ float g_msgW[CAP_BONDxH];   // used as __half (only half occupied)
__device__ float g_ainput[CAP_ATOMxAIN];
__device__ float g_ah[CAP_ATOMxH];
__device__ float g_Wh[CAP_WH];
__device__ float g_Wo[CAP_WO];

// slots: 0=binput 1=msg 2=msgW 3=ainput 4=ah 5=Wh(tf32) 6=Wo(tf32)
__device__ float* g_ptrs[7];

__global__ void init_ptrs()
{
    if (threadIdx.x == 0) {
        g_ptrs[0] = g_binput;
        g_ptrs[1] = g_msg;
        g_ptrs[2] = g_msgW;
        g_ptrs[3] = g_ainput;
        g_ptrs[4] = g_ah;
        g_ptrs[5] = g_Wh;
        g_ptrs[6] = g_Wo;
    }
}

__device__ __forceinline__ uint32_t f2tf32(float x) {
    uint32_t r;
    asm("cvt.rna.tf32.f32 %0, %1;" : "=r"(r) : "f"(x));
    return r;
}
__device__ __forceinline__ float f2tf32f(float x) {
    return __uint_as_float(f2tf32(x));
}

// One-shot: round W_h and W_o to tf32 into scratch.
__global__ void cvt_weights(const float* __restrict__ Wh, int nh,
                            const float* __restrict__ Wo, int no)
{
    float* dWh = g_ptrs[5];
    float* dWo = g_ptrs[6];
    for (int i = blockIdx.x * blockDim.x + threadIdx.x; i < nh + no;
         i += gridDim.x * blockDim.x) {
        if (i < nh) dWh[i] = f2tf32f(Wh[i]);
        else        dWo[i - nh] = f2tf32f(Wo[i - nh]);
    }
}

// ============================================================================
// tf32 tensor-core GEMM, cp.async 4-stage pipeline.
//   Out = epi( A[M,K](slot,lda) @ B[Kreal,N](slot) + C0 + bias )
// epi: optional relu; output fp32 or fp16.
// 128x128 tile, BK=16, 256 threads (8 warps, 32x64 warp tile, m16n8k8).
// ============================================================================
#define TBM 128
#define TBN 128
#define TBK 16
#define ASTR 20
#define BSTR 132
#define A_WORDS (TBM * ASTR)
#define B_WORDS (TBK * BSTR)
#define STAGE_WORDS (A_WORDS + B_WORDS)
#define NSTAGE 4
#define GEMM_SMEM_BYTES (NSTAGE * STAGE_WORDS * 4)

__device__ __forceinline__ void cp16(void* sdst, const void* gsrc, bool p) {
    uint32_t d = (uint32_t)__cvta_generic_to_shared(sdst);
    int sz = p ? 16 : 0;
    asm volatile("cp.async.cg.shared.global [%0], [%1], 16, %2;\n"
                 :: "r"(d), "l"(gsrc), "r"(sz));
}
__device__ __forceinline__ void cp_commit() {
    asm volatile("cp.async.commit_group;\n");
}
template<int NN> __device__ __forceinline__ void cp_wait() {
    asm volatile("cp.async.wait_group %0;\n" :: "n"(NN));
}

__device__ __forceinline__ void mma_tf32(float c[4],
                                         uint32_t a0, uint32_t a1, uint32_t a2, uint32_t a3,
                                         uint32_t b0, uint32_t b1)
{
    asm volatile(
        "mma.sync.aligned.m16n8k8.row.col.f32.tf32.tf32.f32 "
        "{%0,%1,%2,%3}, {%4,%5,%6,%7}, {%8,%9}, {%0,%1,%2,%3};\n"
        : "+f"(c[0]), "+f"(c[1]), "+f"(c[2]), "+f"(c[3])
        : "r"(a0), "r"(a1), "r"(a2), "r"(a3), "r"(b0), "r"(b1));
}

extern __shared__ uint32_t smem_u[];

__global__ __launch_bounds__(256)
void gemm_tf32(int Aslot, int lda,
               int Bslot,
               int C0slot,                       // -1 = none
               const float* __restrict__ bias,   // [N] or null
               int OutSlot,
               int do_relu, int out_half,
               int M, int N, int K, int Kreal)
{
    const float* __restrict__ A  = g_ptrs[Aslot];
    const float* __restrict__ B  = g_ptrs[Bslot];
    const float* __restrict__ C0 = (C0slot >= 0) ? g_ptrs[C0slot] : nullptr;
    float* __restrict__ Out      = g_ptrs[OutSlot];

    const int tid = threadIdx.x;
    const int bm = blockIdx.y * TBM;
    const int bn = blockIdx.x * TBN;

    const int wid  = tid >> 5;
    const int lane = tid & 31;
    const int wm = (wid & 3) * 32;
    const int wn = (wid >> 2) * 64;
    const int g   = lane >> 2;
    const int tig = lane & 3;

    const int ar = tid >> 2;
    const int ac = (tid & 3) * 4;

    const int nk = K / TBK;

    auto issue = [&](int t) {
        const int s = t % NSTAGE;
        uint32_t* As = smem_u + s * STAGE_WORDS;
        uint32_t* Bs = As + A_WORDS;
        const int k0 = t * TBK;
        #pragma unroll
        for (int i = 0; i < 2; i++) {
            int arow = ar + i * 64;
            int grow = bm + arow;
            bool pa = (grow < M);
            const float* srcA = &A[(long long)(pa ? grow : 0) * lda + k0 + ac];
            cp16(&As[arow * ASTR + ac], srcA, pa);

            int f = tid + i * 256;
            int br_ = f >> 5;
            int bc_ = (f & 31) * 4;
            int gk = k0 + br_, gn = bn + bc_;
            bool pb = (gk < Kreal) && (gn < N);
            const float* srcB = &B[(long long)(pb ? gk : 0) * N + (pb ? gn : 0)];
            cp16(&Bs[br_ * BSTR + bc_], srcB, pb);
        }
    };

    float acc[2][8][4];
    #pragma unroll
    for (int mt = 0; mt < 2; mt++)
        #pragma unroll
        for (int nt = 0; nt < 8; nt++)
            #pragma unroll
            for (int r = 0; r < 4; r++) acc[mt][nt][r] = 0.f;

    #pragma unroll
    for (int t = 0; t < NSTAGE - 1; t++) { issue(t); cp_commit(); }
    cp_wait<NSTAGE - 2>();
    __syncthreads();

    for (int t = 0; t < nk; t++) {
        const uint32_t* As = smem_u + (t % NSTAGE) * STAGE_WORDS;
        const uint32_t* Bs = As + A_WORDS;

        #pragma unroll
        for (int kk = 0; kk < TBK; kk += 8) {
            uint32_t a[2][4];
            #pragma unroll
            for (int mt = 0; mt < 2; mt++) {
                int m0 = wm + mt * 16;
                a[mt][0] = As[(m0 + g    ) * ASTR + kk + tig];
                a[mt][1] = As[(m0 + g + 8) * ASTR + kk + tig];
                a[mt][2] = As[(m0 + g    ) * ASTR + kk + tig + 4];
                a[mt][3] = As[(m0 + g + 8) * ASTR + kk + tig + 4];
            }
            uint32_t b[8][2];
            #pragma unroll
            for (int nt = 0; nt < 8; nt++) {
                int n0 = wn + nt * 8;
                b[nt][0] = Bs[(kk + tig    ) * BSTR + n0 + g];
                b[nt][1] = Bs[(kk + tig + 4) * BSTR + n0 + g];
            }
            #pragma unroll
            for (int mt = 0; mt < 2; mt++)
                #pragma unroll
                for (int nt = 0; nt < 8; nt++)
                    mma_tf32(acc[mt][nt], a[mt][0], a[mt][1], a[mt][2], a[mt][3],
                             b[nt][0], b[nt][1]);
        }

        if (t + NSTAGE - 1 < nk) issue(t + NSTAGE - 1);
        cp_commit();
        cp_wait<NSTAGE - 2>();
        __syncthreads();
    }

    // epilogue
    #pragma unroll
    for (int mt = 0; mt < 2; mt++) {
        #pragma unroll
        for (int nt = 0; nt < 8; nt++) {
            int col = bn + wn + nt * 8 + tig * 2;
            if (col >= N) continue;
            #pragma unroll
            for (int h = 0; h < 2; h++) {
                int row = bm + wm + mt * 16 + g + h * 8;
                if (row >= M) continue;
                long long o = (long long)row * N + col;
                float v0 = acc[mt][nt][h * 2 + 0];
                float v1 = acc[mt][nt][h * 2 + 1];
                if (C0)   { v0 += C0[o];     v1 += C0[o + 1]; }
                if (bias) { v0 += bias[col]; v1 += bias[col + 1]; }
                if (do_relu) { v0 = fmaxf(v0, 0.f); v1 = fmaxf(v1, 0.f); }
                if (out_half) {
                    *(__half2*)&((__half*)Out)[o] = __floats2half2_rn(v0, v1);
                } else {
                    *(float2*)&Out[o] = make_float2(v0, v1);
                }
            }
        }
    }
}

// ============================================================================
// fp32 SIMT GEMM (binput: K=49, memory-bound, full precision)
// Craw = raw; Crelu = tf32(relu(raw))   (Crelu feeds the tf32 GEMM A operand)
// ============================================================================
#define BM 128
#define BN 128
#define BKK 8
#define TM 8
#define TN 8

__global__ __launch_bounds__(256)
void gemm_f32(const float* __restrict__ A, int lda,
              const float* __restrict__ B,
              int CrawSlot, int CreluSlot,
              int M, int N, int K)
{
    float* __restrict__ Craw  = g_ptrs[CrawSlot];
    float* __restrict__ Crelu = g_ptrs[CreluSlot];

    __shared__ float As[BKK][BM];
    __shared__ float Bs[BKK][BN];

    const int tid = threadIdx.x;
    const int bm = blockIdx.y * BM;
    const int bn = blockIdx.x * BN;
    const int tx = tid & 15;
    const int ty = tid >> 4;
    const int ar = tid >> 1;
    const int ac = (tid & 1) * 4;
    const int br = tid >> 5;
    const int bc = (tid & 31) * 4;

    float acc[TM][TN];
    #pragma unroll
    for (int i = 0; i < TM; i++)
        #pragma unroll
        for (int j = 0; j < TN; j++) acc[i][j] = 0.f;

    for (int k0 = 0; k0 < K; k0 += BKK) {
        {
            long long row = (long long)(bm + ar);
            const bool rok = (bm + ar) < M;
            #pragma unroll
            for (int j = 0; j < 4; j++) {
                int k = k0 + ac + j;
                float v = 0.f;
                if (rok && k < K) v = A[row * lda + k];
                As[ac + j][ar] = v;
            }
        }
        {
            int k = k0 + br;
            float4 v = make_float4(0.f, 0.f, 0.f, 0.f);
            if (k < K) {
                if (bn + bc + 3 < N) {
                    v = *(const float4*)&B[(long long)k * N + bn + bc];
                } else {
                    float* pv = (float*)&v;
                    #pragma unroll
                    for (int j = 0; j < 4; j++) {
                        int n = bn + bc + j;
                        pv[j] = (n < N) ? B[(long long)k * N + n] : 0.f;
                    }
                }
            }
            *(float4*)&Bs[br][bc] = v;
        }
        __syncthreads();

        #pragma unroll
        for (int kk = 0; kk < BKK; kk++) {
            float a[TM], b[TN];
            #pragma unroll
            for (int i = 0; i < TM; i++) a[i] = As[kk][ty * TM + i];
            #pragma unroll
            for (int j = 0; j < TN; j++) b[j] = Bs[kk][tx * TN + j];
            #pragma unroll
            for (int i = 0; i < TM; i++)
                #pragma unroll
                for (int j = 0; j < TN; j++)
                    acc[i][j] += a[i] * b[j];
        }
        __syncthreads();
    }

    #pragma unroll
    for (int i = 0; i < TM; i++) {
        int mi = bm + ty * TM + i;
        if (mi >= M) continue;
        long long mrow = (long long)mi * N;
        #pragma unroll
        for (int j = 0; j < TN; j++) {
            int n = bn + tx * TN + j;
            if (n >= N) continue;
            float v = acc[i][j];
            Craw[mrow + n] = v;
            Crelu[mrow + n] = f2tf32f(fmaxf(v, 0.f));
        }
    }
}

// ----------------------------------------------------------------------------
// Fused gather/update: msg[b] = tf32(relu(binput[b] + Σ_j msgW[bgraph[b,j]]))
// msgW is fp16. 2 bonds per 128-thread block, 8 columns per thread iteration.
// ----------------------------------------------------------------------------
__global__ __launch_bounds__(128)
void gather_update(const int* __restrict__ bgraph,
                   int n_bonds, int H, int max_nb)
{
    const float* __restrict__ binput = g_ptrs[0];
    float* __restrict__ msg          = g_ptrs[1];
    const __half* __restrict__ msgW  = (const __half*)g_ptrs[2];

    const int half_ = threadIdx.x >> 6;
    const int lane  = threadIdx.x & 63;
    const long long b = (long long)blockIdx.x * 2 + half_;
    const bool valid = (b < n_bonds);

    __shared__ int idx[2][8];
    if (valid && lane < max_nb)
        idx[half_][lane] = bgraph[b * max_nb + lane];
    __syncthreads();
    if (!valid) return;

    const int HC = H >> 3;   // 8-halfs chunks (H % 8 == 0 for H=448)
    for (int c = lane; c < HC; c += 64) {
        float s[8];
        #pragma unroll
        for (int q = 0; q < 8; q++) s[q] = 0.f;

        #pragma unroll 6
        for (int j = 0; j < max_nb; j++) {
            const uint4 u = __ldg((const uint4*)&msgW[(long long)idx[half_][j] * H + c * 8]);
            float2 f0 = __half22float2(*(const __half2*)&u.x);
            float2 f1 = __half22float2(*(const __half2*)&u.y);
            float2 f2 = __half22float2(*(const __half2*)&u.z);
            float2 f3 = __half22float2(*(const __half2*)&u.w);
            s[0] += f0.x; s[1] += f0.y; s[2] += f1.x; s[3] += f1.y;
            s[4] += f2.x; s[5] += f2.y; s[6] += f3.x; s[7] += f3.y;
        }

        const long long o = b * H + c * 8;
        float4 b0 = *(const float4*)&binput[o];
        float4 b1 = *(const float4*)&binput[o + 4];
        float4 o0, o1;
        o0.x = f2tf32f(fmaxf(s[0] + b0.x, 0.f));
        o0.y = f2tf32f(fmaxf(s[1] + b0.y, 0.f));
        o0.z = f2tf32f(fmaxf(s[2] + b0.z, 0.f));
        o0.w = f2tf32f(fmaxf(s[3] + b0.w, 0.f));
        o1.x = f2tf32f(fmaxf(s[4] + b1.x, 0.f));
        o1.y = f2tf32f(fmaxf(s[5] + b1.y, 0.f));
        o1.z = f2tf32f(fmaxf(s[6] + b1.z, 0.f));
        o1.w = f2tf32f(fmaxf(s[7] + b1.w, 0.f));
        *(float4*)&msg[o]     = o0;
        *(float4*)&msg[o + 4] = o1;
    }
}

// ----------------------------------------------------------------------------
// ainput[a] = tf32_round([ fatoms[a] | sum_j msg[agraph[a][j]] | 0 pad ])
// ----------------------------------------------------------------------------
__global__ __launch_bounds__(128)
void build_ainput(const float* __restrict__ fatoms,
                  const int* __restrict__ agraph,
                  int n_atoms, int H, int atom_dim, int max_nb)
{
    const float* __restrict__ msg = g_ptrs[1];
    float* __restrict__ ainput    = g_ptrs[3];

    const long long a = blockIdx.x;
    __shared__ int idx[8];
    if (threadIdx.x < max_nb)
        idx[threadIdx.x] = agraph[a * max_nb + threadIdx.x];
    __syncthreads();

    const int AIN = atom_dim + H;
    float* out = ainput + a * AIN_PAD;
    for (int c = threadIdx.x; c < atom_dim; c += blockDim.x)
        out[c] = f2tf32f(fatoms[a * atom_dim + c]);
    for (int c = threadIdx.x; c < H; c += blockDim.x) {
        float s = 0.f;
        #pragma unroll 6
        for (int j = 0; j < max_nb; j++) s += __ldg(&msg[(long long)idx[j] * H + c]);
        out[atom_dim + c] = f2tf32f(s);
    }
    for (int c = AIN + threadIdx.x; c < AIN_PAD; c += blockDim.x)
        out[c] = 0.f;
}

// ----------------------------------------------------------------------------
// Per-molecule mean over sorted mol_idx.
// ----------------------------------------------------------------------------
__global__ __launch_bounds__(256)
void mol_mean(const int* __restrict__ mol_idx,
              float* __restrict__ out,
              int n_atoms, int H)
{
    const float* __restrict__ ah = g_ptrs[4];
    const int m = blockIdx.x;

    int l = 0, r = n_atoms;
    while (l < r) { int mid = (l + r) >> 1; if (mol_idx[mid] < m) l = mid + 1; else r = mid; }
    const int start = l;
    r = n_atoms;
    while (l < r) { int mid = (l + r) >> 1; if (mol_idx[mid] < m + 1) l = mid + 1; else r = mid; }
    const int end = l;
    const float inv = 1.f / fmaxf((float)(end - start), 1.f);

    for (int c = threadIdx.x; c < H; c += blockDim.x) {
        float s = 0.f;
        for (int a = start; a < end; a++) s += ah[(long long)a * H + c];
        out[(long long)m * H + c] = s * inv;
    }
}

// ----------------------------------------------------------------------------
// Launch
// ----------------------------------------------------------------------------
static inline dim3 g128(int M, int N) {
    return dim3((N + 127) / 128, (M + 127) / 128);
}

extern "C" void kernel_launch(void* const* d_in, const int* in_sizes, int n_in,
                              void* d_out, int out_size)
{
    const float* fatoms  = (const float*)d_in[0];
    const float* fbonds  = (const float*)d_in[1];
    const float* W_i     = (const float*)d_in[2];
    const float* W_h     = (const float*)d_in[3];
    const float* W_o     = (const float*)d_in[4];
    const float* b_o     = (const float*)d_in[5];
    const int*   agraph  = (const int*)d_in[6];
    const int*   bgraph  = (const int*)d_in[7];
    const int*   mol_idx = (const int*)d_in[8];

    const int n_atoms  = in_sizes[8];
    const int H        = in_sizes[5];
    const int BOND_IN  = in_sizes[2] / H;
    const int n_bonds  = in_sizes[1] / BOND_IN;
    const int ATOM_DIM = in_sizes[0] / n_atoms;
    const int MAX_NB   = in_sizes[6] / n_atoms;
    const int n_mols   = out_size / H;
    const int AIN      = ATOM_DIM + H;   // 486

    cudaFuncSetAttribute(gemm_tf32, cudaFuncAttributeMaxDynamicSharedMemorySize,
                         GEMM_SMEM_BYTES);

    init_ptrs<<<1, 32>>>();
    cvt_weights<<<256, 256>>>(W_h, H * H, W_o, AIN * H);

    // 1. binput = fbonds @ W_i (raw) ; msg = tf32(relu(binput))
    gemm_f32<<<g128(n_bonds, H), 256>>>(
        fbonds, BOND_IN, W_i,
        /*Craw*/0, /*Crelu*/1,
        n_bonds, H, BOND_IN);

    // 2. message passing: 4x ( msgW = msg@Wh [fp16 out] ; fused gather+add+relu )
    for (int it = 0; it < DEPTH - 1; it++) {
        gemm_tf32<<<g128(n_bonds, H), 256, GEMM_SMEM_BYTES>>>(
            /*Aslot*/1, /*lda*/H, /*Bslot*/5,
            /*C0slot*/-1, /*bias*/nullptr, /*OutSlot*/2,
            /*relu*/0, /*half*/1,
            n_bonds, H, H, H);
        gather_update<<<(n_bonds + 1) / 2, 128>>>(bgraph, n_bonds, H, MAX_NB);
    }

    // 3. atom readout
    build_ainput<<<n_atoms, 128>>>(fatoms, agraph, n_atoms, H, ATOM_DIM, MAX_NB);
    gemm_tf32<<<g128(n_atoms, H), 256, GEMM_SMEM_BYTES>>>(
        /*Aslot*/3, /*lda*/AIN_PAD, /*Bslot*/6,
        /*C0slot*/-1, /*bias*/b_o, /*OutSlot*/4,
        /*relu*/1, /*half*/0,
        n_atoms, H, AIN_PAD, AIN);

    // 4. per-molecule mean pooling
    mol_mean<<<n_mols, 256>>>(mol_idx, (float*)d_out, n_atoms, H);
}

// round 7
// speedup vs baseline: 5.1402x; 1.5566x over previous
#include <cuda_runtime.h>
#include <cuda_fp16.h>
#include <cstdint>

// ----------------------------------------------------------------------------
// MPN (chemprop D-MPNN), round 7: fp16 tensor-core GEMMs (m16n8k16 + ldmatrix,
// XOR-swizzled smem, cp.async 4-stage). fp16 mantissa == tf32 mantissa, fp32
// accumulate -> same rounding class as the passing tf32 version.
//   binput(f32) = fbonds_h @ Wi_h ; msg(f16) = relu(binput)
//   4x: msgW(f16) = msg @ Wh_h ; msg = f16(relu(binput + Σ_j msgW[bgraph]))
//   ainput(f16) = [fatoms | Σ_j msg[agraph] | 0pad] ; ah(f32) = relu(@Wo_h + b_o)
//   out[m] = mean over atoms of molecule m
// Index arrays are int32 (JAX downgrades int64). Scratch in __device__ globals.
// ----------------------------------------------------------------------------

#define DEPTH 5
#define AIN_PAD 512       // 486 padded to multiple of 64 (BK)
#define KPAD_BI 64        // 49 padded to 64

#define CAP_BONDxH 72000000ll
#define CAP_ATOMxAIN 40000000ll   // floats; holds 80000*512 halfs
#define CAP_ATOMxH 36000000ll
#define CAP_W 250000
#define CAP_FBH 6000000ll         // floats; holds 160001*64 halfs

__device__ float g_binput[CAP_BONDxH];
__device__ float g_msg[CAP_BONDxH];     // used as __half
__device__ float g_msgW[CAP_BONDxH];    // used as __half
__device__ float g_ainput[CAP_ATOMxAIN];// used as __half
__device__ float g_ah[CAP_ATOMxH];
__device__ float g_Wh[CAP_W];           // __half [448][448]
__device__ float g_Wo[CAP_W];           // __half [486][448]
__device__ float g_Wi[CAP_W];           // __half [49][448]
__device__ float g_fbh[CAP_FBH];        // __half [M][64]

// slots: 0=binput 1=msg 2=msgW 3=ainput 4=ah 5=Wh 6=Wo 7=Wi 8=fbonds_h
__device__ float* g_ptrs[9];

__global__ void init_ptrs()
{
    if (threadIdx.x == 0) {
        g_ptrs[0] = g_binput; g_ptrs[1] = g_msg;  g_ptrs[2] = g_msgW;
        g_ptrs[3] = g_ainput; g_ptrs[4] = g_ah;   g_ptrs[5] = g_Wh;
        g_ptrs[6] = g_Wo;     g_ptrs[7] = g_Wi;   g_ptrs[8] = g_fbh;
    }
}

// One-shot weight conversions fp32 -> fp16 (same [K][N] layout).
__global__ void cvt_weights(const float* __restrict__ Wh, int nh,
                            const float* __restrict__ Wo, int no,
                            const float* __restrict__ Wi, int ni)
{
    __half* dWh = (__half*)g_ptrs[5];
    __half* dWo = (__half*)g_ptrs[6];
    __half* dWi = (__half*)g_ptrs[7];
    int total = nh + no + ni;
    for (int i = blockIdx.x * blockDim.x + threadIdx.x; i < total;
         i += gridDim.x * blockDim.x) {
        if (i < nh)           dWh[i] = __float2half_rn(Wh[i]);
        else if (i < nh + no) dWo[i - nh] = __float2half_rn(Wo[i - nh]);
        else                  dWi[i - nh - no] = __float2half_rn(Wi[i - nh - no]);
    }
}

// fbonds [M][49] f32 -> fbonds_h [M][64] f16 (pad zero)
__global__ void cvt_fbonds(const float* __restrict__ fb, int M, int Kin)
{
    __half* out = (__half*)g_ptrs[8];
    long long total = (long long)M * KPAD_BI;
    for (long long i = (long long)blockIdx.x * blockDim.x + threadIdx.x; i < total;
         i += (long long)gridDim.x * blockDim.x) {
        int col = (int)(i & (KPAD_BI - 1));
        long long row = i >> 6;
        out[i] = (col < Kin) ? __float2half_rn(fb[row * Kin + col]) : __half(0.f);
    }
}

// ============================================================================
// fp16 tensor-core GEMM: Out = epi( A[M,K]h(lda) @ B[Kreal,N]h + bias )
// 128x128 tile, BK=64 halfs, 256 threads, 8 warps (4m x 2n), warp 32x64,
// mma.m16n8k16, ldmatrix.x4(+trans), XOR swizzle, cp.async 4-stage.
//   OutSlot: primary (fp32 or fp16 per out_half; relu per do_relu)
//   Out2Slot: optional fp16 relu copy (-1 = none)   [binput/msg split]
// ============================================================================
#define TBM 128
#define TBN 128
#define TBK 64
#define A_BYTES (TBM * TBK * 2)            // 16384
#define B_BYTES (TBK * TBN * 2)            // 16384
#define STAGE_BYTES (A_BYTES + B_BYTES)    // 32768
#define NSTAGE 4
#define GEMM_SMEM_BYTES (NSTAGE * STAGE_BYTES)

__device__ __forceinline__ void cp16s(uint32_t sdst, const void* gsrc, bool p) {
    int sz = p ? 16 : 0;
    asm volatile("cp.async.cg.shared.global [%0], [%1], 16, %2;\n"
                 :: "r"(sdst), "l"(gsrc), "r"(sz));
}
__device__ __forceinline__ void cp_commit() {
    asm volatile("cp.async.commit_group;\n");
}
template<int NN> __device__ __forceinline__ void cp_wait() {
    asm volatile("cp.async.wait_group %0;\n" :: "n"(NN));
}
__device__ __forceinline__ void ldsm_x4(uint32_t* r, uint32_t addr) {
    asm volatile("ldmatrix.sync.aligned.m8n8.x4.shared.b16 {%0,%1,%2,%3}, [%4];"
                 : "=r"(r[0]), "=r"(r[1]), "=r"(r[2]), "=r"(r[3]) : "r"(addr));
}
__device__ __forceinline__ void ldsm_x4_t(uint32_t* r, uint32_t addr) {
    asm volatile("ldmatrix.sync.aligned.m8n8.x4.trans.shared.b16 {%0,%1,%2,%3}, [%4];"
                 : "=r"(r[0]), "=r"(r[1]), "=r"(r[2]), "=r"(r[3]) : "r"(addr));
}
__device__ __forceinline__ void mma_f16(float c[4], const uint32_t a[4],
                                        uint32_t b0, uint32_t b1)
{
    asm volatile(
        "mma.sync.aligned.m16n8k16.row.col.f32.f16.f16.f32 "
        "{%0,%1,%2,%3}, {%4,%5,%6,%7}, {%8,%9}, {%0,%1,%2,%3};\n"
        : "+f"(c[0]), "+f"(c[1]), "+f"(c[2]), "+f"(c[3])
        : "r"(a[0]), "r"(a[1]), "r"(a[2]), "r"(a[3]), "r"(b0), "r"(b1));
}

extern __shared__ uint8_t smem_raw[];

__global__ __launch_bounds__(256)
void gemm_f16(int Aslot, int lda,
              int Bslot,
              const float* __restrict__ bias,
              int OutSlot, int Out2Slot,
              int do_relu, int out_half,
              int M, int N, int K, int Kreal)     // K mult of 64
{
    const __half* __restrict__ Ah = (const __half*)g_ptrs[Aslot];
    const __half* __restrict__ Bh = (const __half*)g_ptrs[Bslot];
    float* __restrict__ Out  = g_ptrs[OutSlot];
    __half* __restrict__ Out2 = (Out2Slot >= 0) ? (__half*)g_ptrs[Out2Slot] : nullptr;

    const uint32_t smem_base = (uint32_t)__cvta_generic_to_shared(smem_raw);

    const int tid = threadIdx.x;
    const int bm = blockIdx.y * TBM;
    const int bn = blockIdx.x * TBN;

    const int wid  = tid >> 5;
    const int lane = tid & 31;
    const int wm = (wid & 3) * 32;
    const int wn = (wid >> 2) * 64;
    const int g   = lane >> 2;
    const int tig = lane & 3;
    const int l15 = lane & 15;
    const int lhi = lane >> 4;

    const int nk = K / TBK;

    auto issue = [&](int t) {
        if (t >= nk) return;
        const uint32_t sb = smem_base + (t % NSTAGE) * STAGE_BYTES;
        const int k0 = t * TBK;
        #pragma unroll
        for (int i = 0; i < 4; i++) {
            int f = tid + i * 256;
            // A: 128 rows x 8 chunks(16B)
            int arow = f >> 3, ac = f & 7;
            int aphys = ac ^ (arow & 7);
            int grow = bm + arow;
            bool pa = grow < M;
            const __half* srcA = Ah + (long long)(pa ? grow : 0) * lda + k0 + ac * 8;
            cp16s(sb + arow * 128 + aphys * 16, srcA, pa);
            // B: 64 rows x 16 chunks(16B)
            int krow = f >> 4, bc = f & 15;
            int bphys = bc ^ (krow & 7);
            int gk = k0 + krow, gn = bn + bc * 8;
            bool pb = (gk < Kreal) && (gn < N);
            const __half* srcB = Bh + (long long)(pb ? gk : 0) * N + (pb ? gn : 0);
            cp16s(sb + A_BYTES + krow * 256 + bphys * 16, srcB, pb);
        }
    };

    float acc[2][8][4];
    #pragma unroll
    for (int mt = 0; mt < 2; mt++)
        #pragma unroll
        for (int nt = 0; nt < 8; nt++)
            #pragma unroll
            for (int r = 0; r < 4; r++) acc[mt][nt][r] = 0.f;

    #pragma unroll
    for (int t = 0; t < NSTAGE - 1; t++) { issue(t); cp_commit(); }
    cp_wait<NSTAGE - 2>();
    __syncthreads();

    for (int t = 0; t < nk; t++) {
        const uint32_t sA = smem_base + (t % NSTAGE) * STAGE_BYTES;
        const uint32_t sB = sA + A_BYTES;

        #pragma unroll
        for (int step = 0; step < 4; step++) {
            uint32_t a[2][4];
            #pragma unroll
            for (int mt = 0; mt < 2; mt++) {
                int row = wm + mt * 16 + l15;
                int chunk = step * 2 + lhi;
                int phys = chunk ^ (row & 7);
                ldsm_x4(a[mt], sA + row * 128 + phys * 16);
            }
            uint32_t b[8][2];
            #pragma unroll
            for (int p = 0; p < 4; p++) {
                int krow = step * 16 + l15;
                int nchunk = ((wn + p * 16) >> 3) + lhi;
                int phys = nchunk ^ (krow & 7);
                uint32_t r[4];
                ldsm_x4_t(r, sB + krow * 256 + phys * 16);
                b[2 * p][0] = r[0]; b[2 * p][1] = r[1];
                b[2 * p + 1][0] = r[2]; b[2 * p + 1][1] = r[3];
            }
            #pragma unroll
            for (int mt = 0; mt < 2; mt++)
                #pragma unroll
                for (int nt = 0; nt < 8; nt++)
                    mma_f16(acc[mt][nt], a[mt], b[nt][0], b[nt][1]);
        }

        issue(t + NSTAGE - 1);
        cp_commit();
        cp_wait<NSTAGE - 2>();
        __syncthreads();
    }

    // epilogue: c0,c1 -> (row g, cols 2tig,2tig+1); c2,c3 -> row g+8
    #pragma unroll
    for (int mt = 0; mt < 2; mt++) {
        #pragma unroll
        for (int nt = 0; nt < 8; nt++) {
            int col = bn + wn + nt * 8 + tig * 2;
            if (col >= N) continue;
            #pragma unroll
            for (int h = 0; h < 2; h++) {
                int row = bm + wm + mt * 16 + g + h * 8;
                if (row >= M) continue;
                long long o = (long long)row * N + col;
                float v0 = acc[mt][nt][h * 2 + 0];
                float v1 = acc[mt][nt][h * 2 + 1];
                if (bias) { v0 += bias[col]; v1 += bias[col + 1]; }
                float r0 = fmaxf(v0, 0.f), r1 = fmaxf(v1, 0.f);
                if (do_relu) { v0 = r0; v1 = r1; }
                if (out_half) {
                    *(__half2*)&((__half*)Out)[o] = __floats2half2_rn(v0, v1);
                } else {
                    *(float2*)&Out[o] = make_float2(v0, v1);
                }
                if (Out2) {
                    *(__half2*)&Out2[o] = __floats2half2_rn(r0, r1);
                }
            }
        }
    }
}

// ----------------------------------------------------------------------------
// Fused gather/update: msg[b] = f16(relu(binput[b] + Σ_j msgW[bgraph[b,j]]))
// msgW/msg fp16, binput fp32. 2 bonds per 128-thread block, 8 cols/lane-iter.
// ----------------------------------------------------------------------------
__global__ __launch_bounds__(128)
void gather_update(const int* __restrict__ bgraph,
                   int n_bonds, int H, int max_nb)
{
    const float* __restrict__ binput = g_ptrs[0];
    __half* __restrict__ msg         = (__half*)g_ptrs[1];
    const __half* __restrict__ msgW  = (const __half*)g_ptrs[2];

    const int half_ = threadIdx.x >> 6;
    const int lane  = threadIdx.x & 63;
    const long long b = (long long)blockIdx.x * 2 + half_;
    const bool valid = (b < n_bonds);

    __shared__ int idx[2][8];
    if (valid && lane < max_nb)
        idx[half_][lane] = bgraph[b * max_nb + lane];
    __syncthreads();
    if (!valid) return;

    const int HC = H >> 3;
    for (int c = lane; c < HC; c += 64) {
        float s[8];
        #pragma unroll
        for (int q = 0; q < 8; q++) s[q] = 0.f;

        #pragma unroll 6
        for (int j = 0; j < max_nb; j++) {
            const uint4 u = __ldg((const uint4*)&msgW[(long long)idx[half_][j] * H + c * 8]);
            float2 f0 = __half22float2(*(const __half2*)&u.x);
            float2 f1 = __half22float2(*(const __half2*)&u.y);
            float2 f2 = __half22float2(*(const __half2*)&u.z);
            float2 f3 = __half22float2(*(const __half2*)&u.w);
            s[0] += f0.x; s[1] += f0.y; s[2] += f1.x; s[3] += f1.y;
            s[4] += f2.x; s[5] += f2.y; s[6] += f3.x; s[7] += f3.y;
        }

        const long long o = b * H + c * 8;
        float4 b0 = *(const float4*)&binput[o];
        float4 b1 = *(const float4*)&binput[o + 4];
        __half2 h0 = __floats2half2_rn(fmaxf(s[0] + b0.x, 0.f), fmaxf(s[1] + b0.y, 0.f));
        __half2 h1 = __floats2half2_rn(fmaxf(s[2] + b0.z, 0.f), fmaxf(s[3] + b0.w, 0.f));
        __half2 h2 = __floats2half2_rn(fmaxf(s[4] + b1.x, 0.f), fmaxf(s[5] + b1.y, 0.f));
        __half2 h3 = __floats2half2_rn(fmaxf(s[6] + b1.z, 0.f), fmaxf(s[7] + b1.w, 0.f));
        uint4 u;
        u.x = *(uint32_t*)&h0; u.y = *(uint32_t*)&h1;
        u.z = *(uint32_t*)&h2; u.w = *(uint32_t*)&h3;
        *(uint4*)&msg[o] = u;
    }
}

// ----------------------------------------------------------------------------
// ainput[a] = f16([ fatoms[a] | Σ_j msg[agraph[a,j]] | 0 pad ]), stride AIN_PAD.
// 2 atoms per 128-thread block.
// ----------------------------------------------------------------------------
__global__ __launch_bounds__(128)
void build_ainput(const float* __restrict__ fatoms,
                  const int* __restrict__ agraph,
                  int n_atoms, int H, int atom_dim, int max_nb)
{
    const __half* __restrict__ msg = (const __half*)g_ptrs[1];
    __half* __restrict__ ainput    = (__half*)g_ptrs[3];

    const int half_ = threadIdx.x >> 6;
    const int lane  = threadIdx.x & 63;
    const long long a = (long long)blockIdx.x * 2 + half_;
    const bool valid = (a < n_atoms);

    __shared__ int idx[2][8];
    if (valid && lane < max_nb)
        idx[half_][lane] = agraph[a * max_nb + lane];
    __syncthreads();
    if (!valid) return;

    const int AIN = atom_dim + H;
    __half* out = ainput + a * AIN_PAD;
    for (int c = lane; c < atom_dim; c += 64)
        out[c] = __float2half_rn(fatoms[a * atom_dim + c]);

    const int HC = H >> 3;
    for (int c = lane; c < HC; c += 64) {
        float s[8];
        #pragma unroll
        for (int q = 0; q < 8; q++) s[q] = 0.f;
        #pragma unroll 6
        for (int j = 0; j < max_nb; j++) {
            const uint4 u = __ldg((const uint4*)&msg[(long long)idx[half_][j] * H + c * 8]);
            float2 f0 = __half22float2(*(const __half2*)&u.x);
            float2 f1 = __half22float2(*(const __half2*)&u.y);
            float2 f2 = __half22float2(*(const __half2*)&u.z);
            float2 f3 = __half22float2(*(const __half2*)&u.w);
            s[0] += f0.x; s[1] += f0.y; s[2] += f1.x; s[3] += f1.y;
            s[4] += f2.x; s[5] += f2.y; s[6] += f3.x; s[7] += f3.y;
        }
        __half2 h0 = __floats2half2_rn(s[0], s[1]);
        __half2 h1 = __floats2half2_rn(s[2], s[3]);
        __half2 h2 = __floats2half2_rn(s[4], s[5]);
        __half2 h3 = __floats2half2_rn(s[6], s[7]);
        __half2* dst = (__half2*)&out[atom_dim + c * 8];   // atom_dim even -> 4B aligned
        dst[0] = h0; dst[1] = h1; dst[2] = h2; dst[3] = h3;
    }
    for (int c = AIN + lane; c < AIN_PAD; c += 64)
        out[c] = __half(0.f);
}

// ----------------------------------------------------------------------------
// Per-molecule mean over sorted mol_idx (binary search, no atomics).
// ----------------------------------------------------------------------------
__global__ __launch_bounds__(256)
void mol_mean(const int* __restrict__ mol_idx,
              float* __restrict__ out,
              int n_atoms, int H)
{
    const float* __restrict__ ah = g_ptrs[4];
    const int m = blockIdx.x;

    int l = 0, r = n_atoms;
    while (l < r) { int mid = (l + r) >> 1; if (mol_idx[mid] < m) l = mid + 1; else r = mid; }
    const int start = l;
    r = n_atoms;
    while (l < r) { int mid = (l + r) >> 1; if (mol_idx[mid] < m + 1) l = mid + 1; else r = mid; }
    const int end = l;
    const float inv = 1.f / fmaxf((float)(end - start), 1.f);

    for (int c = threadIdx.x; c < H; c += blockDim.x) {
        float s = 0.f;
        for (int a = start; a < end; a++) s += ah[(long long)a * H + c];
        out[(long long)m * H + c] = s * inv;
    }
}

// ----------------------------------------------------------------------------
// Launch
// ----------------------------------------------------------------------------
static inline dim3 g128(int M, int N) {
    return dim3((N + 127) / 128, (M + 127) / 128);
}

extern "C" void kernel_launch(void* const* d_in, const int* in_sizes, int n_in,
                              void* d_out, int out_size)
{
    const float* fatoms  = (const float*)d_in[0];
    const float* fbonds  = (const float*)d_in[1];
    const float* W_i     = (const float*)d_in[2];
    const float* W_h     = (const float*)d_in[3];
    const float* W_o     = (const float*)d_in[4];
    const float* b_o     = (const float*)d_in[5];
    const int*   agraph  = (const int*)d_in[6];
    const int*   bgraph  = (const int*)d_in[7];
    const int*   mol_idx = (const int*)d_in[8];

    const int n_atoms  = in_sizes[8];
    const int H        = in_sizes[5];
    const int BOND_IN  = in_sizes[2] / H;            // 49
    const int n_bonds  = in_sizes[1] / BOND_IN;
    const int ATOM_DIM = in_sizes[0] / n_atoms;      // 38
    const int MAX_NB   = in_sizes[6] / n_atoms;      // 6
    const int n_mols   = out_size / H;
    const int AIN      = ATOM_DIM + H;               // 486

    cudaFuncSetAttribute(gemm_f16, cudaFuncAttributeMaxDynamicSharedMemorySize,
                         GEMM_SMEM_BYTES);

    init_ptrs<<<1, 32>>>();
    cvt_weights<<<256, 256>>>(W_h, H * H, W_o, AIN * H, W_i, BOND_IN * H);
    cvt_fbonds<<<512, 256>>>(fbonds, n_bonds, BOND_IN);

    // 1. binput(f32 raw) + msg(f16 relu) = fbonds_h @ Wi_h
    gemm_f16<<<g128(n_bonds, H), 256, GEMM_SMEM_BYTES>>>(
        /*A*/8, /*lda*/KPAD_BI, /*B*/7,
        /*bias*/nullptr, /*Out*/0, /*Out2*/1,
        /*relu*/0, /*half*/0,
        n_bonds, H, KPAD_BI, BOND_IN);

    // 2. message passing: 4x ( msgW = msg@Wh [f16] ; fused gather+add+relu )
    for (int it = 0; it < DEPTH - 1; it++) {
        gemm_f16<<<g128(n_bonds, H), 256, GEMM_SMEM_BYTES>>>(
            /*A*/1, /*lda*/H, /*B*/5,
            /*bias*/nullptr, /*Out*/2, /*Out2*/-1,
            /*relu*/0, /*half*/1,
            n_bonds, H, H, H);
        gather_update<<<(n_bonds + 1) / 2, 128>>>(bgraph, n_bonds, H, MAX_NB);
    }

    // 3. atom readout
    build_ainput<<<(n_atoms + 1) / 2, 128>>>(fatoms, agraph, n_atoms, H, ATOM_DIM, MAX_NB);
    gemm_f16<<<g128(n_atoms, H), 256, GEMM_SMEM_BYTES>>>(
        /*A*/3, /*lda*/AIN_PAD, /*B*/6,
        /*bias*/b_o, /*Out*/4, /*Out2*/-1,
        /*relu*/1, /*half*/0,
        n_atoms, H, AIN_PAD, AIN);

    // 4. per-molecule mean pooling
    mol_mean<<<n_mols, 256>>>(mol_idx, (float*)d_out, n_atoms, H);
}

// round 8
// speedup vs baseline: 6.5002x; 1.2646x over previous
#include <cuda_runtime.h>
#include <cuda_fp16.h>
#include <cstdint>

// ----------------------------------------------------------------------------
// MPN (chemprop D-MPNN), round 8: fp16 MMA GEMM at 2 CTAs/SM (3-stage, 96KB,
// <=128 regs), binput+ah stored fp16 to cut gather/pool traffic.
//   binput(f16) = fbonds_h @ Wi_h ; msg(f16) = relu(binput)
//   4x: msgW(f16) = msg @ Wh_h ; msg = f16(relu(binput + Σ_j msgW[bgraph]))
//   ainput(f16) = [fatoms | Σ_j msg[agraph] | 0pad] ; ah(f16) = relu(@Wo_h + b_o)
//   out[m](f32) = mean over atoms of molecule m
// Index arrays are int32 (JAX downgrades int64). Scratch in __device__ globals.
// ----------------------------------------------------------------------------

#define DEPTH 5
#define AIN_PAD 512       // 486 padded to multiple of 64 (BK)
#define KPAD_BI 64        // 49 padded to 64

#define CAP_BONDxH 72000000ll     // floats; holds as halfs with room to spare
#define CAP_ATOMxAIN 40000000ll
#define CAP_ATOMxH 36000000ll
#define CAP_W 250000
#define CAP_FBH 6000000ll

__device__ float g_binput[CAP_BONDxH];  // used as __half
__device__ float g_msg[CAP_BONDxH];     // used as __half
__device__ float g_msgW[CAP_BONDxH];    // used as __half
__device__ float g_ainput[CAP_ATOMxAIN];// used as __half
__device__ float g_ah[CAP_ATOMxH];      // used as __half
__device__ float g_Wh[CAP_W];           // __half [448][448]
__device__ float g_Wo[CAP_W];           // __half [486][448]
__device__ float g_Wi[CAP_W];           // __half [49][448]
__device__ float g_fbh[CAP_FBH];        // __half [M][64]

// slots: 0=binput 1=msg 2=msgW 3=ainput 4=ah 5=Wh 6=Wo 7=Wi 8=fbonds_h
__device__ float* g_ptrs[9];

__global__ void init_ptrs()
{
    if (threadIdx.x == 0) {
        g_ptrs[0] = g_binput; g_ptrs[1] = g_msg;  g_ptrs[2] = g_msgW;
        g_ptrs[3] = g_ainput; g_ptrs[4] = g_ah;   g_ptrs[5] = g_Wh;
        g_ptrs[6] = g_Wo;     g_ptrs[7] = g_Wi;   g_ptrs[8] = g_fbh;
    }
}

// One-shot weight conversions fp32 -> fp16 (same [K][N] layout).
__global__ void cvt_weights(const float* __restrict__ Wh, int nh,
                            const float* __restrict__ Wo, int no,
                            const float* __restrict__ Wi, int ni)
{
    __half* dWh = (__half*)g_ptrs[5];
    __half* dWo = (__half*)g_ptrs[6];
    __half* dWi = (__half*)g_ptrs[7];
    int total = nh + no + ni;
    for (int i = blockIdx.x * blockDim.x + threadIdx.x; i < total;
         i += gridDim.x * blockDim.x) {
        if (i < nh)           dWh[i] = __float2half_rn(Wh[i]);
        else if (i < nh + no) dWo[i - nh] = __float2half_rn(Wo[i - nh]);
        else                  dWi[i - nh - no] = __float2half_rn(Wi[i - nh - no]);
    }
}

// fbonds [M][49] f32 -> fbonds_h [M][64] f16 (pad zero)
__global__ void cvt_fbonds(const float* __restrict__ fb, int M, int Kin)
{
    __half* out = (__half*)g_ptrs[8];
    long long total = (long long)M * KPAD_BI;
    for (long long i = (long long)blockIdx.x * blockDim.x + threadIdx.x; i < total;
         i += (long long)gridDim.x * blockDim.x) {
        int col = (int)(i & (KPAD_BI - 1));
        long long row = i >> 6;
        out[i] = (col < Kin) ? __float2half_rn(fb[row * Kin + col]) : __half(0.f);
    }
}

// ============================================================================
// fp16 tensor-core GEMM: Out = epi( A[M,K]h(lda) @ B[Kreal,N]h + bias )
// 128x128 tile, BK=64 halfs, 256 threads, 8 warps (4m x 2n), warp 32x64,
// mma.m16n8k16, ldmatrix.x4(+trans), XOR swizzle, cp.async 3-stage, 2 CTAs/SM.
//   OutSlot: primary (fp32 or fp16 per out_half; relu per do_relu)
//   Out2Slot: optional fp16 relu copy (-1 = none)
// ============================================================================
#define TBM 128
#define TBN 128
#define TBK 64
#define A_BYTES (TBM * TBK * 2)            // 16384
#define B_BYTES (TBK * TBN * 2)            // 16384
#define STAGE_BYTES (A_BYTES + B_BYTES)    // 32768
#define NSTAGE 3
#define GEMM_SMEM_BYTES (NSTAGE * STAGE_BYTES)   // 98304

__device__ __forceinline__ void cp16s(uint32_t sdst, const void* gsrc, bool p) {
    int sz = p ? 16 : 0;
    asm volatile("cp.async.cg.shared.global [%0], [%1], 16, %2;\n"
                 :: "r"(sdst), "l"(gsrc), "r"(sz));
}
__device__ __forceinline__ void cp_commit() {
    asm volatile("cp.async.commit_group;\n");
}
template<int NN> __device__ __forceinline__ void cp_wait() {
    asm volatile("cp.async.wait_group %0;\n" :: "n"(NN));
}
__device__ __forceinline__ void ldsm_x4(uint32_t* r, uint32_t addr) {
    asm volatile("ldmatrix.sync.aligned.m8n8.x4.shared.b16 {%0,%1,%2,%3}, [%4];"
                 : "=r"(r[0]), "=r"(r[1]), "=r"(r[2]), "=r"(r[3]) : "r"(addr));
}
__device__ __forceinline__ void ldsm_x4_t(uint32_t* r, uint32_t addr) {
    asm volatile("ldmatrix.sync.aligned.m8n8.x4.trans.shared.b16 {%0,%1,%2,%3}, [%4];"
                 : "=r"(r[0]), "=r"(r[1]), "=r"(r[2]), "=r"(r[3]) : "r"(addr));
}
__device__ __forceinline__ void mma_f16(float c[4], const uint32_t a[4],
                                        uint32_t b0, uint32_t b1)
{
    asm volatile(
        "mma.sync.aligned.m16n8k16.row.col.f32.f16.f16.f32 "
        "{%0,%1,%2,%3}, {%4,%5,%6,%7}, {%8,%9}, {%0,%1,%2,%3};\n"
        : "+f"(c[0]), "+f"(c[1]), "+f"(c[2]), "+f"(c[3])
        : "r"(a[0]), "r"(a[1]), "r"(a[2]), "r"(a[3]), "r"(b0), "r"(b1));
}

extern __shared__ uint8_t smem_raw[];

__global__ __launch_bounds__(256, 2)
void gemm_f16(int Aslot, int lda,
              int Bslot,
              const float* __restrict__ bias,
              int OutSlot, int Out2Slot,
              int do_relu, int out_half,
              int M, int N, int K, int Kreal)     // K mult of 64
{
    const __half* __restrict__ Ah = (const __half*)g_ptrs[Aslot];
    const __half* __restrict__ Bh = (const __half*)g_ptrs[Bslot];
    float* __restrict__ Out  = g_ptrs[OutSlot];
    __half* __restrict__ Out2 = (Out2Slot >= 0) ? (__half*)g_ptrs[Out2Slot] : nullptr;

    const uint32_t smem_base = (uint32_t)__cvta_generic_to_shared(smem_raw);

    const int tid = threadIdx.x;
    const int bm = blockIdx.y * TBM;
    const int bn = blockIdx.x * TBN;

    const int wid  = tid >> 5;
    const int lane = tid & 31;
    const int wm = (wid & 3) * 32;
    const int wn = (wid >> 2) * 64;
    const int g   = lane >> 2;
    const int tig = lane & 3;
    const int l15 = lane & 15;
    const int lhi = lane >> 4;

    const int nk = K / TBK;

    auto issue = [&](int t) {
        if (t >= nk) return;
        const uint32_t sb = smem_base + (t % NSTAGE) * STAGE_BYTES;
        const int k0 = t * TBK;
        #pragma unroll
        for (int i = 0; i < 4; i++) {
            int f = tid + i * 256;
            // A: 128 rows x 8 chunks(16B)
            int arow = f >> 3, ac = f & 7;
            int aphys = ac ^ (arow & 7);
            int grow = bm + arow;
            bool pa = grow < M;
            const __half* srcA = Ah + (long long)(pa ? grow : 0) * lda + k0 + ac * 8;
            cp16s(sb + arow * 128 + aphys * 16, srcA, pa);
            // B: 64 rows x 16 chunks(16B)
            int krow = f >> 4, bc = f & 15;
            int bphys = bc ^ (krow & 7);
            int gk = k0 + krow, gn = bn + bc * 8;
            bool pb = (gk < Kreal) && (gn < N);
            const __half* srcB = Bh + (long long)(pb ? gk : 0) * N + (pb ? gn : 0);
            cp16s(sb + A_BYTES + krow * 256 + bphys * 16, srcB, pb);
        }
    };

    float acc[2][8][4];
    #pragma unroll
    for (int mt = 0; mt < 2; mt++)
        #pragma unroll
        for (int nt = 0; nt < 8; nt++)
            #pragma unroll
            for (int r = 0; r < 4; r++) acc[mt][nt][r] = 0.f;

    #pragma unroll
    for (int t = 0; t < NSTAGE - 1; t++) { issue(t); cp_commit(); }
    cp_wait<NSTAGE - 2>();
    __syncthreads();

    for (int t = 0; t < nk; t++) {
        const uint32_t sA = smem_base + (t % NSTAGE) * STAGE_BYTES;
        const uint32_t sB = sA + A_BYTES;

        #pragma unroll
        for (int step = 0; step < 4; step++) {
            uint32_t a[2][4];
            #pragma unroll
            for (int mt = 0; mt < 2; mt++) {
                int row = wm + mt * 16 + l15;
                int chunk = step * 2 + lhi;
                int phys = chunk ^ (row & 7);
                ldsm_x4(a[mt], sA + row * 128 + phys * 16);
            }
            uint32_t b[8][2];
            #pragma unroll
            for (int p = 0; p < 4; p++) {
                int krow = step * 16 + l15;
                int nchunk = ((wn + p * 16) >> 3) + lhi;
                int phys = nchunk ^ (krow & 7);
                uint32_t r[4];
                ldsm_x4_t(r, sB + krow * 256 + phys * 16);
                b[2 * p][0] = r[0]; b[2 * p][1] = r[1];
                b[2 * p + 1][0] = r[2]; b[2 * p + 1][1] = r[3];
            }
            #pragma unroll
            for (int mt = 0; mt < 2; mt++)
                #pragma unroll
                for (int nt = 0; nt < 8; nt++)
                    mma_f16(acc[mt][nt], a[mt], b[nt][0], b[nt][1]);
        }

        issue(t + NSTAGE - 1);
        cp_commit();
        cp_wait<NSTAGE - 2>();
        __syncthreads();
    }

    // epilogue
    #pragma unroll
    for (int mt = 0; mt < 2; mt++) {
        #pragma unroll
        for (int nt = 0; nt < 8; nt++) {
            int col = bn + wn + nt * 8 + tig * 2;
            if (col >= N) continue;
            #pragma unroll
            for (int h = 0; h < 2; h++) {
                int row = bm + wm + mt * 16 + g + h * 8;
                if (row >= M) continue;
                long long o = (long long)row * N + col;
                float v0 = acc[mt][nt][h * 2 + 0];
                float v1 = acc[mt][nt][h * 2 + 1];
                if (bias) { v0 += bias[col]; v1 += bias[col + 1]; }
                float r0 = fmaxf(v0, 0.f), r1 = fmaxf(v1, 0.f);
                if (do_relu) { v0 = r0; v1 = r1; }
                if (out_half) {
                    *(__half2*)&((__half*)Out)[o] = __floats2half2_rn(v0, v1);
                } else {
                    *(float2*)&Out[o] = make_float2(v0, v1);
                }
                if (Out2) {
                    *(__half2*)&Out2[o] = __floats2half2_rn(r0, r1);
                }
            }
        }
    }
}

// ----------------------------------------------------------------------------
// Fused gather/update: msg[b] = f16(relu(binput[b] + Σ_j msgW[bgraph[b,j]]))
// All fp16 storage, fp32 accumulation. 2 bonds/block, 8 cols per lane-iter.
// ----------------------------------------------------------------------------
__global__ __launch_bounds__(128)
void gather_update(const int* __restrict__ bgraph,
                   int n_bonds, int H, int max_nb)
{
    const __half* __restrict__ binput = (const __half*)g_ptrs[0];
    __half* __restrict__ msg          = (__half*)g_ptrs[1];
    const __half* __restrict__ msgW   = (const __half*)g_ptrs[2];

    const int half_ = threadIdx.x >> 6;
    const int lane  = threadIdx.x & 63;
    const long long b = (long long)blockIdx.x * 2 + half_;
    const bool valid = (b < n_bonds);

    __shared__ int idx[2][8];
    if (valid && lane < max_nb)
        idx[half_][lane] = bgraph[b * max_nb + lane];
    __syncthreads();
    if (!valid) return;

    const int HC = H >> 3;
    for (int c = lane; c < HC; c += 64) {
        float s[8];
        #pragma unroll
        for (int q = 0; q < 8; q++) s[q] = 0.f;

        #pragma unroll 6
        for (int j = 0; j < max_nb; j++) {
            const uint4 u = __ldg((const uint4*)&msgW[(long long)idx[half_][j] * H + c * 8]);
            float2 f0 = __half22float2(*(const __half2*)&u.x);
            float2 f1 = __half22float2(*(const __half2*)&u.y);
            float2 f2 = __half22float2(*(const __half2*)&u.z);
            float2 f3 = __half22float2(*(const __half2*)&u.w);
            s[0] += f0.x; s[1] += f0.y; s[2] += f1.x; s[3] += f1.y;
            s[4] += f2.x; s[5] += f2.y; s[6] += f3.x; s[7] += f3.y;
        }

        const long long o = b * H + c * 8;
        const uint4 ub = *(const uint4*)&binput[o];
        float2 g0 = __half22float2(*(const __half2*)&ub.x);
        float2 g1 = __half22float2(*(const __half2*)&ub.y);
        float2 g2 = __half22float2(*(const __half2*)&ub.z);
        float2 g3 = __half22float2(*(const __half2*)&ub.w);
        __half2 h0 = __floats2half2_rn(fmaxf(s[0] + g0.x, 0.f), fmaxf(s[1] + g0.y, 0.f));
        __half2 h1 = __floats2half2_rn(fmaxf(s[2] + g1.x, 0.f), fmaxf(s[3] + g1.y, 0.f));
        __half2 h2 = __floats2half2_rn(fmaxf(s[4] + g2.x, 0.f), fmaxf(s[5] + g2.y, 0.f));
        __half2 h3 = __floats2half2_rn(fmaxf(s[6] + g3.x, 0.f), fmaxf(s[7] + g3.y, 0.f));
        uint4 u;
        u.x = *(uint32_t*)&h0; u.y = *(uint32_t*)&h1;
        u.z = *(uint32_t*)&h2; u.w = *(uint32_t*)&h3;
        *(uint4*)&msg[o] = u;
    }
}

// ----------------------------------------------------------------------------
// ainput[a] = f16([ fatoms[a] | Σ_j msg[agraph[a,j]] | 0 pad ]), stride AIN_PAD.
// 2 atoms per 128-thread block.
// ----------------------------------------------------------------------------
__global__ __launch_bounds__(128)
void build_ainput(const float* __restrict__ fatoms,
                  const int* __restrict__ agraph,
                  int n_atoms, int H, int atom_dim, int max_nb)
{
    const __half* __restrict__ msg = (const __half*)g_ptrs[1];
    __half* __restrict__ ainput    = (__half*)g_ptrs[3];

    const int half_ = threadIdx.x >> 6;
    const int lane  = threadIdx.x & 63;
    const long long a = (long long)blockIdx.x * 2 + half_;
    const bool valid = (a < n_atoms);

    __shared__ int idx[2][8];
    if (valid && lane < max_nb)
        idx[half_][lane] = agraph[a * max_nb + lane];
    __syncthreads();
    if (!valid) return;

    const int AIN = atom_dim + H;
    __half* out = ainput + a * AIN_PAD;
    for (int c = lane; c < atom_dim; c += 64)
        out[c] = __float2half_rn(fatoms[a * atom_dim + c]);

    const int HC = H >> 3;
    for (int c = lane; c < HC; c += 64) {
        float s[8];
        #pragma unroll
        for (int q = 0; q < 8; q++) s[q] = 0.f;
        #pragma unroll 6
        for (int j = 0; j < max_nb; j++) {
            const uint4 u = __ldg((const uint4*)&msg[(long long)idx[half_][j] * H + c * 8]);
            float2 f0 = __half22float2(*(const __half2*)&u.x);
            float2 f1 = __half22float2(*(const __half2*)&u.y);
            float2 f2 = __half22float2(*(const __half2*)&u.z);
            float2 f3 = __half22float2(*(const __half2*)&u.w);
            s[0] += f0.x; s[1] += f0.y; s[2] += f1.x; s[3] += f1.y;
            s[4] += f2.x; s[5] += f2.y; s[6] += f3.x; s[7] += f3.y;
        }
        __half2 h0 = __floats2half2_rn(s[0], s[1]);
        __half2 h1 = __floats2half2_rn(s[2], s[3]);
        __half2 h2 = __floats2half2_rn(s[4], s[5]);
        __half2 h3 = __floats2half2_rn(s[6], s[7]);
        __half2* dst = (__half2*)&out[atom_dim + c * 8];
        dst[0] = h0; dst[1] = h1; dst[2] = h2; dst[3] = h3;
    }
    for (int c = AIN + lane; c < AIN_PAD; c += 64)
        out[c] = __half(0.f);
}

// ----------------------------------------------------------------------------
// Per-molecule mean over sorted mol_idx (binary search, no atomics). ah is f16.
// ----------------------------------------------------------------------------
__global__ __launch_bounds__(256)
void mol_mean(const int* __restrict__ mol_idx,
              float* __restrict__ out,
              int n_atoms, int H)
{
    const __half* __restrict__ ah = (const __half*)g_ptrs[4];
    const int m = blockIdx.x;

    int l = 0, r = n_atoms;
    while (l < r) { int mid = (l + r) >> 1; if (mol_idx[mid] < m) l = mid + 1; else r = mid; }
    const int start = l;
    r = n_atoms;
    while (l < r) { int mid = (l + r) >> 1; if (mol_idx[mid] < m + 1) l = mid + 1; else r = mid; }
    const int end = l;
    const float inv = 1.f / fmaxf((float)(end - start), 1.f);

    for (int c = threadIdx.x; c < H; c += blockDim.x) {
        float s = 0.f;
        for (int a = start; a < end; a++)
            s += __half2float(ah[(long long)a * H + c]);
        out[(long long)m * H + c] = s * inv;
    }
}

// ----------------------------------------------------------------------------
// Launch
// ----------------------------------------------------------------------------
static inline dim3 g128(int M, int N) {
    return dim3((N + 127) / 128, (M + 127) / 128);
}

extern "C" void kernel_launch(void* const* d_in, const int* in_sizes, int n_in,
                              void* d_out, int out_size)
{
    const float* fatoms  = (const float*)d_in[0];
    const float* fbonds  = (const float*)d_in[1];
    const float* W_i     = (const float*)d_in[2];
    const float* W_h     = (const float*)d_in[3];
    const float* W_o     = (const float*)d_in[4];
    const float* b_o     = (const float*)d_in[5];
    const int*   agraph  = (const int*)d_in[6];
    const int*   bgraph  = (const int*)d_in[7];
    const int*   mol_idx = (const int*)d_in[8];

    const int n_atoms  = in_sizes[8];
    const int H        = in_sizes[5];
    const int BOND_IN  = in_sizes[2] / H;            // 49
    const int n_bonds  = in_sizes[1] / BOND_IN;
    const int ATOM_DIM = in_sizes[0] / n_atoms;      // 38
    const int MAX_NB   = in_sizes[6] / n_atoms;      // 6
    const int n_mols   = out_size / H;
    const int AIN      = ATOM_DIM + H;               // 486

    cudaFuncSetAttribute(gemm_f16, cudaFuncAttributeMaxDynamicSharedMemorySize,
                         GEMM_SMEM_BYTES);

    init_ptrs<<<1, 32>>>();
    cvt_weights<<<256, 256>>>(W_h, H * H, W_o, AIN * H, W_i, BOND_IN * H);
    cvt_fbonds<<<512, 256>>>(fbonds, n_bonds, BOND_IN);

    // 1. binput(f16 raw) + msg(f16 relu) = fbonds_h @ Wi_h
    gemm_f16<<<g128(n_bonds, H), 256, GEMM_SMEM_BYTES>>>(
        /*A*/8, /*lda*/KPAD_BI, /*B*/7,
        /*bias*/nullptr, /*Out*/0, /*Out2*/1,
        /*relu*/0, /*half*/1,
        n_bonds, H, KPAD_BI, BOND_IN);

    // 2. message passing: 4x ( msgW = msg@Wh [f16] ; fused gather+add+relu )
    for (int it = 0; it < DEPTH - 1; it++) {
        gemm_f16<<<g128(n_bonds, H), 256, GEMM_SMEM_BYTES>>>(
            /*A*/1, /*lda*/H, /*B*/5,
            /*bias*/nullptr, /*Out*/2, /*Out2*/-1,
            /*relu*/0, /*half*/1,
            n_bonds, H, H, H);
        gather_update<<<(n_bonds + 1) / 2, 128>>>(bgraph, n_bonds, H, MAX_NB);
    }

    // 3. atom readout (ah f16)
    build_ainput<<<(n_atoms + 1) / 2, 128>>>(fatoms, agraph, n_atoms, H, ATOM_DIM, MAX_NB);
    gemm_f16<<<g128(n_atoms, H), 256, GEMM_SMEM_BYTES>>>(
        /*A*/3, /*lda*/AIN_PAD, /*B*/6,
        /*bias*/b_o, /*Out*/4, /*Out2*/-1,
        /*relu*/1, /*half*/1,
        n_atoms, H, AIN_PAD, AIN);

    // 4. per-molecule mean pooling (f32 out)
    mol_mean<<<n_mols, 256>>>(mol_idx, (float*)d_out, n_atoms, H);
}